// round 3
// baseline (speedup 1.0000x reference)
#include <cuda_runtime.h>
#include <cuda_bf16.h>
#include <math.h>
#include <stdint.h>

#define BB 32
#define CCH 512
#define SEQ 256
#define NITER 25
#define DM 2048
#define DI 512
#define NHE 8
#define HD 64
#define NS 512
#define MEMN 25
#define MHN 64
#define OD 1000

// ----------------- static device scratch -----------------
__device__ float g_xT[BB * SEQ * CCH];        // (b,s,c)
__device__ float g_kv[BB * SEQ * DI];         // (b,s,d) post-LN
__device__ float g_KV[BB * SEQ * 2 * DI];     // (b,s,[K|V])
__device__ float g_Wqq[NS * DI];              // q_w @ wq^T  [n][e]
__device__ float g_bqq[DI];
__device__ float g_aoT[DI * DI];              // attn_out_w^T [d][e]
__device__ float g_Was[DI * 2 * DM];          // aoT @ syn_w_top [d][j]
__device__ float g_synb2[2 * DM];
__device__ float g_tp1wt[DM * MEMN * 2 * MHN]; // [d][m*128+h]
__device__ float g_tp2wt[DM * 2 * MHN];        // [d][h*2+o]
__device__ float g_act[BB * DM];
__device__ float g_trace[BB * DM * MEMN];      // ring on last dim
__device__ float g_daa[BB * NS];
__device__ float g_dba[BB * NS];
__device__ float g_dao[BB * NS];
__device__ float g_dbo[BB * NS];
__device__ float g_syncA[BB * NS];
__device__ float g_syncO[BB * NS];
__device__ float g_q[BB * DI];
__device__ float g_attn[BB * DI];
__device__ float g_synp[4 * BB * 2 * DM];      // split-K partials
__device__ float g_pred[BB * OD];

// ----------------- helpers -----------------
__device__ __forceinline__ float warpSum(float v) {
#pragma unroll
    for (int o = 16; o; o >>= 1) v += __shfl_down_sync(0xffffffffu, v, o);
    return v;
}
__device__ __forceinline__ float warpMax(float v) {
#pragma unroll
    for (int o = 16; o; o >>= 1) v = fmaxf(v, __shfl_down_sync(0xffffffffu, v, o));
    return v;
}
template<int NW>
__device__ __forceinline__ float blockSumAll(float v, volatile float* red) {
    float s = warpSum(v);
    __syncthreads();
    if ((threadIdx.x & 31) == 0) red[threadIdx.x >> 5] = s;
    __syncthreads();
    float t = 0.f;
#pragma unroll
    for (int i = 0; i < NW; i++) t += red[i];
    return t;
}
template<int NW>
__device__ __forceinline__ float blockMaxAll(float v, volatile float* red) {
    float s = warpMax(v);
    __syncthreads();
    if ((threadIdx.x & 31) == 0) red[threadIdx.x >> 5] = s;
    __syncthreads();
    float t = -3.4e38f;
#pragma unroll
    for (int i = 0; i < NW; i++) t = fmaxf(t, red[i]);
    return t;
}
__device__ __forceinline__ float sigm(float x) { return 1.f / (1.f + expf(-x)); }

// ----------------- generic transpose (batched 2D) -----------------
__global__ void k_transpose(const float* __restrict__ in, float* __restrict__ out,
                            int R, int Cc) {
    __shared__ float t[32][33];
    int b = blockIdx.z;
    int r0 = blockIdx.y * 32, c0 = blockIdx.x * 32;
    const float* ip = in + (size_t)b * R * Cc;
    float* op = out + (size_t)b * R * Cc;
#pragma unroll
    for (int i = threadIdx.y; i < 32; i += 8) {
        int r = r0 + i, c = c0 + threadIdx.x;
        if (r < R && c < Cc) t[i][threadIdx.x] = ip[(size_t)r * Cc + c];
    }
    __syncthreads();
#pragma unroll
    for (int i = threadIdx.y; i < 32; i += 8) {
        int c = c0 + i, r = r0 + threadIdx.x;
        if (c < Cc && r < R) op[(size_t)c * R + r] = t[threadIdx.x][i];
    }
}

// ----------------- generic tiled GEMM: C = A(MxK) * B + bias -----------------
// transB=0: B is KxN row-major. transB=1: B is NxK row-major.
__global__ void __launch_bounds__(256) k_gemm64(
    const float* __restrict__ A, const float* __restrict__ Bm,
    const float* __restrict__ bias, float* __restrict__ Cm,
    int M, int N, int K, int ldc, int cofs, int transB) {
    __shared__ float As[16][65];
    __shared__ float Bs[16][65];
    int m0 = blockIdx.y * 64, n0 = blockIdx.x * 64;
    int tid = threadIdx.x;
    int tx = tid % 16, ty = tid / 16;
    float acc[4][4] = {};
    for (int k0 = 0; k0 < K; k0 += 16) {
#pragma unroll
        for (int p = 0; p < 4; p++) {
            int m = (tid / 16) + p * 16;
            int k = tid % 16;
            As[k][m] = A[(size_t)(m0 + m) * K + k0 + k];
        }
        if (!transB) {
#pragma unroll
            for (int p = 0; p < 4; p++) {
                int kk = tid / 64 + p * 4;
                int n = tid % 64;
                Bs[kk][n] = Bm[(size_t)(k0 + kk) * N + n0 + n];
            }
        } else {
#pragma unroll
            for (int p = 0; p < 4; p++) {
                int n = tid / 16 + p * 16;
                int kk = tid % 16;
                Bs[kk][n] = Bm[(size_t)(n0 + n) * K + k0 + kk];
            }
        }
        __syncthreads();
#pragma unroll
        for (int k = 0; k < 16; k++) {
            float a[4], b[4];
#pragma unroll
            for (int i = 0; i < 4; i++) a[i] = As[k][ty * 4 + i];
#pragma unroll
            for (int j = 0; j < 4; j++) b[j] = Bs[k][tx * 4 + j];
#pragma unroll
            for (int i = 0; i < 4; i++)
#pragma unroll
                for (int j = 0; j < 4; j++) acc[i][j] += a[i] * b[j];
        }
        __syncthreads();
    }
#pragma unroll
    for (int i = 0; i < 4; i++) {
        int m = m0 + ty * 4 + i;
#pragma unroll
        for (int j = 0; j < 4; j++) {
            int n = n0 + tx * 4 + j;
            float v = acc[i][j] + (bias ? bias[n] : 0.f);
            Cm[(size_t)m * ldc + cofs + n] = v;
        }
    }
}

// ----------------- LN over rows of 512 (in-place) -----------------
__global__ void k_ln512(float* __restrict__ buf, const float* __restrict__ g,
                        const float* __restrict__ bb) {
    __shared__ float red[8];
    float* p = buf + (size_t)blockIdx.x * 512;
    int tid = threadIdx.x;
    float v0 = p[tid], v1 = p[tid + 256];
    float mean = blockSumAll<8>(v0 + v1, red) * (1.f / 512.f);
    float d0 = v0 - mean, d1 = v1 - mean;
    float var = blockSumAll<8>(d0 * d0 + d1 * d1, red) * (1.f / 512.f);
    float inv = rsqrtf(var + 1e-5f);
    p[tid] = d0 * inv * g[tid] + bb[tid];
    p[tid + 256] = d1 * inv * g[tid + 256] + bb[tid + 256];
}

// ----------------- small precomputes -----------------
__global__ void k_bqq(const float* __restrict__ qb, const float* __restrict__ aw,
                      const float* __restrict__ bq) {
    int e = blockIdx.x * 256 + threadIdx.x;
    float s = bq[e];
    for (int d = 0; d < 512; d++) s += qb[d] * aw[(size_t)e * 512 + d];
    g_bqq[e] = s;
}
__global__ void k_synb2(const float* __restrict__ aob, const float* __restrict__ syn_w,
                        const float* __restrict__ syn_b) {
    int j = blockIdx.x * 256 + threadIdx.x;
    float s = syn_b[j];
    for (int e = 0; e < 512; e++) s += aob[e] * syn_w[(size_t)e * 4096 + j];
    g_synb2[j] = s;
}

// ----------------- state init -----------------
__global__ void k_init_state(const float* __restrict__ sas, const float* __restrict__ st) {
    int i = blockIdx.x * 256 + threadIdx.x;  // B*DM
    int d = i & 2047;
    g_act[i] = sas[d];
#pragma unroll
    for (int s = 0; s < 25; s++) g_trace[(size_t)i * 25 + s] = st[d * 25 + s];
}
__global__ void k_init_sync(const float* __restrict__ sas, const int* __restrict__ ol,
                            const int* __restrict__ orr) {
    int i = blockIdx.x * 256 + threadIdx.x;  // B*NS
    int n = i & 511;
    g_daa[i] = 0.f;
    g_dba[i] = 0.f;
    g_dao[i] = sas[ol[n]] * sas[orr[n]];
    g_dbo[i] = 1.f;
}

// ----------------- per-iteration kernels -----------------
__global__ void k_syncA(const float* __restrict__ dec, const int* __restrict__ il,
                        const int* __restrict__ ir) {
    int i = blockIdx.x * 256 + threadIdx.x;
    int b = i >> 9, n = i & 511;
    float ra = expf(-fminf(fmaxf(dec[n], 0.f), 15.f));
    float prod = g_act[b * 2048 + il[n]] * g_act[b * 2048 + ir[n]];
    float daa = ra * g_daa[i] + prod;
    float dba = ra * g_dba[i] + 1.f;
    g_daa[i] = daa;
    g_dba[i] = dba;
    g_syncA[i] = daa * rsqrtf(dba);
}

__global__ void k_qgemm() {
    int e = blockIdx.x * 64 + (threadIdx.x & 63);
    int bl = threadIdx.x >> 6;
    int b = blockIdx.y * 4 + bl;
    __shared__ float sa[4][512];
    for (int i = threadIdx.x; i < 2048; i += 256)
        sa[i >> 9][i & 511] = g_syncA[(blockIdx.y * 4 + (i >> 9)) * 512 + (i & 511)];
    __syncthreads();
    float acc = g_bqq[e];
#pragma unroll 4
    for (int n = 0; n < 512; n++) acc += sa[bl][n] * g_Wqq[(size_t)n * 512 + e];
    g_q[b * 512 + e] = acc;
}

__global__ void k_attn() {
    int b = blockIdx.x >> 3, h = blockIdx.x & 7;
    int tid = threadIdx.x;
    __shared__ float qv[64];
    __shared__ float p[256];
    __shared__ float red[8];
    __shared__ float av[4][64];
    if (tid < 64) qv[tid] = g_q[b * 512 + h * 64 + tid];
    __syncthreads();
    const float* Kp = g_KV + ((size_t)(b * 256 + tid)) * 1024 + h * 64;
    float sc = 0.f;
#pragma unroll
    for (int dd = 0; dd < 64; dd++) sc += qv[dd] * Kp[dd];
    sc *= 0.125f;
    float mall = blockMaxAll<8>(sc, red);
    float e = expf(sc - mall);
    float ssum = blockSumAll<8>(e, red);
    p[tid] = e / ssum;
    __syncthreads();
    int dd = tid & 63, scx = tid >> 6;
    const float* Vp = g_KV + ((size_t)(b * 256 + scx * 64)) * 1024 + 512 + h * 64 + dd;
    float acc = 0.f;
#pragma unroll 8
    for (int j = 0; j < 64; j++) acc += p[scx * 64 + j] * Vp[(size_t)j * 1024];
    av[scx][dd] = acc;
    __syncthreads();
    if (tid < 64)
        g_attn[b * 512 + h * 64 + tid] = av[0][tid] + av[1][tid] + av[2][tid] + av[3][tid];
}

// syn GEMM: out(32x4096) = [attn | act] (32x2560) * [Was ; syn_w_rows512..2559]
// split-K x4 into g_synp
__global__ void __launch_bounds__(256) k_syngemm(const float* __restrict__ syn_w) {
    int n0 = blockIdx.x * 64;
    int kc = blockIdx.y;
    __shared__ float As[64 * 33];
    int tid = threadIdx.x;
    int nn = tid & 63;
    int bg = (tid >> 6) * 8;
    float acc[8] = {};
    for (int ks = 0; ks < 640; ks += 64) {
        int k0 = kc * 640 + ks;
        __syncthreads();
        for (int i = tid; i < 2048; i += 256) {
            int kk = i & 63, bb = i >> 6;
            int k = k0 + kk;
            float av = (k < 512) ? g_attn[bb * 512 + k] : g_act[bb * 2048 + (k - 512)];
            As[kk * 33 + bb] = av;
        }
        __syncthreads();
        const float* Wp = (k0 < 512) ? (g_Was + (size_t)k0 * 4096)
                                     : (syn_w + (size_t)k0 * 4096);
#pragma unroll 8
        for (int kk = 0; kk < 64; kk++) {
            float w = Wp[(size_t)kk * 4096 + n0 + nn];
#pragma unroll
            for (int i2 = 0; i2 < 8; i2++) acc[i2] += As[kk * 33 + bg + i2] * w;
        }
    }
#pragma unroll
    for (int i2 = 0; i2 < 8; i2++)
        g_synp[((size_t)kc * 32 + bg + i2) * 4096 + n0 + nn] = acc[i2];
}

// reduce split-K + GLU + LN + write state into trace ring slot
__global__ void k_glu_ln_trace(const float* __restrict__ lng, const float* __restrict__ lnb,
                               int wslot) {
    int b = blockIdx.x, tid = threadIdx.x;  // 512 threads
    __shared__ float red[16];
    float v[4];
    float s = 0.f;
#pragma unroll
    for (int q = 0; q < 4; q++) {
        int jj = tid + q * 512;
        float a = g_synb2[jj], gg = g_synb2[jj + 2048];
#pragma unroll
        for (int c = 0; c < 4; c++) {
            a += g_synp[((size_t)c * 32 + b) * 4096 + jj];
            gg += g_synp[((size_t)c * 32 + b) * 4096 + jj + 2048];
        }
        v[q] = a * sigm(gg);
        s += v[q];
    }
    float mean = blockSumAll<16>(s, red) * (1.f / 2048.f);
    float s2 = 0.f;
#pragma unroll
    for (int q = 0; q < 4; q++) {
        float d = v[q] - mean;
        s2 += d * d;
    }
    float var = blockSumAll<16>(s2, red) * (1.f / 2048.f);
    float inv = rsqrtf(var + 1e-5f);
#pragma unroll
    for (int q = 0; q < 4; q++) {
        int jj = tid + q * 512;
        float st = (v[q] - mean) * inv * lng[jj] + lnb[jj];
        g_trace[((size_t)b * 2048 + jj) * 25 + wslot] = st;
    }
}

// fused per-neuron NLM: tp1 -> GLU -> tp2 -> GLU -> act
__global__ void __launch_bounds__(256) k_nlm(const float* __restrict__ tp1b,
                                             const float* __restrict__ tp2b, int wslot) {
    int d = blockIdx.x;
    __shared__ float w1s[3200];
    __shared__ float b1s[128];
    __shared__ float w2s[128];
    __shared__ float b2s[2];
    __shared__ float ts[32 * 25];
    __shared__ float red[8][32][2];
    int tid = threadIdx.x;
    {
        const float4* src = (const float4*)(g_tp1wt + (size_t)d * 3200);
        float4* dst = (float4*)w1s;
        for (int i = tid; i < 800; i += 256) dst[i] = src[i];
    }
    if (tid < 128) {
        b1s[tid] = tp1b[d * 128 + tid];
        w2s[tid] = g_tp2wt[d * 128 + tid];
    }
    if (tid < 2) b2s[tid] = tp2b[d * 2 + tid];
    for (int i = tid; i < 800; i += 256) {
        int b = i / 25, m = i % 25;
        int slot = wslot + 1 + m;
        if (slot >= 25) slot -= 25;
        ts[b * 25 + m] = g_trace[((size_t)b * 2048 + d) * 25 + slot];
    }
    __syncthreads();
    int lane = tid & 31;  // batch
    int wi = tid >> 5;    // h-group
    int h0 = wi * 8;
    float a[8] = {}, gg[8] = {};
#pragma unroll
    for (int m = 0; m < 25; m++) {
        float tr = ts[lane * 25 + m];
        float4 a0 = *(const float4*)&w1s[m * 128 + h0];
        float4 a1 = *(const float4*)&w1s[m * 128 + h0 + 4];
        float4 g0 = *(const float4*)&w1s[m * 128 + h0 + 64];
        float4 g1 = *(const float4*)&w1s[m * 128 + h0 + 68];
        a[0] += tr * a0.x; a[1] += tr * a0.y; a[2] += tr * a0.z; a[3] += tr * a0.w;
        a[4] += tr * a1.x; a[5] += tr * a1.y; a[6] += tr * a1.z; a[7] += tr * a1.w;
        gg[0] += tr * g0.x; gg[1] += tr * g0.y; gg[2] += tr * g0.z; gg[3] += tr * g0.w;
        gg[4] += tr * g1.x; gg[5] += tr * g1.y; gg[6] += tr * g1.z; gg[7] += tr * g1.w;
    }
    float p0 = 0.f, p1 = 0.f;
#pragma unroll
    for (int j = 0; j < 8; j++) {
        float hv = (a[j] + b1s[h0 + j]) * sigm(gg[j] + b1s[h0 + 64 + j]);
        p0 += hv * w2s[(h0 + j) * 2];
        p1 += hv * w2s[(h0 + j) * 2 + 1];
    }
    red[wi][lane][0] = p0;
    red[wi][lane][1] = p1;
    __syncthreads();
    if (wi == 0) {
        float z0 = b2s[0], z1 = b2s[1];
#pragma unroll
        for (int k = 0; k < 8; k++) {
            z0 += red[k][lane][0];
            z1 += red[k][lane][1];
        }
        g_act[(size_t)lane * 2048 + d] = z0 * sigm(z1);
    }
}

__global__ void k_syncO(const float* __restrict__ dec, const int* __restrict__ il,
                        const int* __restrict__ ir, float* __restrict__ dout, int t) {
    int i = blockIdx.x * 256 + threadIdx.x;
    int b = i >> 9, n = i & 511;
    float ro = expf(-fminf(fmaxf(dec[n], 0.f), 15.f));
    float prod = g_act[b * 2048 + il[n]] * g_act[b * 2048 + ir[n]];
    float dao = ro * g_dao[i] + prod;
    float dbo = ro * g_dbo[i] + 1.f;
    g_dao[i] = dao;
    g_dbo[i] = dbo;
    float so = dao * rsqrtf(dbo);
    g_syncO[i] = so;
    if (t == 24) dout[800000 + 1600 + (size_t)b * 512 + n] = so;
}

__global__ void k_outgemm(const float* __restrict__ out_w, const float* __restrict__ out_b) {
    int o = blockIdx.x * 256 + threadIdx.x;
    int b0 = blockIdx.y * 4;
    __shared__ float so[4][512];
    for (int i = threadIdx.x; i < 2048; i += 256)
        so[i >> 9][i & 511] = g_syncO[(b0 + (i >> 9)) * 512 + (i & 511)];
    __syncthreads();
    if (o >= 1000) return;
    float a0 = 0.f, a1 = 0.f, a2 = 0.f, a3 = 0.f;
#pragma unroll 4
    for (int n = 0; n < 512; n++) {
        float w = out_w[(size_t)n * 1000 + o];
        a0 += so[0][n] * w;
        a1 += so[1][n] * w;
        a2 += so[2][n] * w;
        a3 += so[3][n] * w;
    }
    float ob = out_b[o];
    g_pred[(size_t)(b0 + 0) * 1000 + o] = a0 + ob;
    g_pred[(size_t)(b0 + 1) * 1000 + o] = a1 + ob;
    g_pred[(size_t)(b0 + 2) * 1000 + o] = a2 + ob;
    g_pred[(size_t)(b0 + 3) * 1000 + o] = a3 + ob;
}

__global__ void k_entropy(float* __restrict__ dout, int t) {
    int b = blockIdx.x, tid = threadIdx.x;
    __shared__ float red[8];
    float mx = -3.4e38f;
    for (int o = tid; o < 1000; o += 256) mx = fmaxf(mx, g_pred[b * 1000 + o]);
    mx = blockMaxAll<8>(mx, red);
    float s = 0.f;
    for (int o = tid; o < 1000; o += 256) s += expf(g_pred[b * 1000 + o] - mx);
    s = blockSumAll<8>(s, red);
    float lse = mx + logf(s);
    float s2 = 0.f;
    for (int o = tid; o < 1000; o += 256) {
        float pv = g_pred[b * 1000 + o];
        float v = pv - lse;
        s2 += expf(v) * v;
        dout[(size_t)b * 25000 + (size_t)o * 25 + t] = pv;
    }
    s2 = blockSumAll<8>(s2, red);
    if (tid == 0) {
        float ne = -s2 / logf(1000.f);
        dout[800000 + (size_t)b * 50 + t] = ne;
        dout[800000 + (size_t)b * 50 + 25 + t] = 1.f - ne;
    }
}

// ----------------- host launcher -----------------
extern "C" void kernel_launch(void* const* d_in, const int* in_sizes, int n_in,
                              void* d_out, int out_size) {
    const float* x = (const float*)d_in[0];
    const float* kv_w = (const float*)d_in[1];
    const float* kv_b = (const float*)d_in[2];
    const float* kv_ln_g = (const float*)d_in[3];
    const float* kv_ln_b = (const float*)d_in[4];
    const float* q_w = (const float*)d_in[5];
    const float* q_b = (const float*)d_in[6];
    const float* attn_in_w = (const float*)d_in[7];
    const float* attn_in_b = (const float*)d_in[8];
    const float* attn_out_w = (const float*)d_in[9];
    const float* attn_out_b = (const float*)d_in[10];
    const float* syn_w = (const float*)d_in[11];
    const float* syn_b = (const float*)d_in[12];
    const float* syn_ln_g = (const float*)d_in[13];
    const float* syn_ln_b = (const float*)d_in[14];
    const float* tp1_w = (const float*)d_in[15];
    const float* tp1_b = (const float*)d_in[16];
    const float* tp2_w = (const float*)d_in[17];
    const float* tp2_b = (const float*)d_in[18];
    const float* sas = (const float*)d_in[19];
    const float* start_trace = (const float*)d_in[20];
    const float* decay_action = (const float*)d_in[21];
    const float* decay_out = (const float*)d_in[22];
    const float* out_w = (const float*)d_in[23];
    const float* out_b = (const float*)d_in[24];
    const int* idx_al = (const int*)d_in[25];
    const int* idx_ar = (const int*)d_in[26];
    const int* idx_ol = (const int*)d_in[27];
    const int* idx_or = (const int*)d_in[28];
    float* dout = (float*)d_out;

    float *p_xT, *p_kv, *p_KV, *p_aoT, *p_Was, *p_Wqq, *p_tp1wt, *p_tp2wt;
    cudaGetSymbolAddress((void**)&p_xT, g_xT);
    cudaGetSymbolAddress((void**)&p_kv, g_kv);
    cudaGetSymbolAddress((void**)&p_KV, g_KV);
    cudaGetSymbolAddress((void**)&p_aoT, g_aoT);
    cudaGetSymbolAddress((void**)&p_Was, g_Was);
    cudaGetSymbolAddress((void**)&p_Wqq, g_Wqq);
    cudaGetSymbolAddress((void**)&p_tp1wt, g_tp1wt);
    cudaGetSymbolAddress((void**)&p_tp2wt, g_tp2wt);

    // ---- preamble ----
    k_transpose<<<dim3(8, 16, 32), dim3(32, 8)>>>(x, p_xT, 512, 256);            // x -> (b,s,c)
    k_gemm64<<<dim3(8, 128), 256>>>(p_xT, kv_w, kv_b, p_kv, 8192, 512, 512, 512, 0, 0);
    k_ln512<<<8192, 256>>>(p_kv, kv_ln_g, kv_ln_b);
    k_gemm64<<<dim3(8, 128), 256>>>(p_kv, attn_in_w + 512 * 512, attn_in_b + 512,
                                    p_KV, 8192, 512, 512, 1024, 0, 1);           // K
    k_gemm64<<<dim3(8, 128), 256>>>(p_kv, attn_in_w + 1024 * 512, attn_in_b + 1024,
                                    p_KV, 8192, 512, 512, 1024, 512, 1);         // V
    k_transpose<<<dim3(16, 16, 1), dim3(32, 8)>>>(attn_out_w, p_aoT, 512, 512);
    k_gemm64<<<dim3(64, 8), 256>>>(p_aoT, syn_w, (const float*)nullptr, p_Was,
                                   512, 4096, 512, 4096, 0, 0);                  // W_as fold
    k_gemm64<<<dim3(8, 8), 256>>>(q_w, attn_in_w, (const float*)nullptr, p_Wqq,
                                  512, 512, 512, 512, 0, 1);                     // W_qq fold
    k_bqq<<<2, 256>>>(q_b, attn_in_w, attn_in_b);
    k_synb2<<<16, 256>>>(attn_out_b, syn_w, syn_b);
    k_transpose<<<dim3(64, 100, 1), dim3(32, 8)>>>(tp1_w, p_tp1wt, 3200, 2048);
    k_transpose<<<dim3(64, 4, 1), dim3(32, 8)>>>(tp2_w, p_tp2wt, 128, 2048);
    k_init_state<<<256, 256>>>(sas, start_trace);
    k_init_sync<<<64, 256>>>(sas, idx_ol, idx_or);

    // ---- 25 recurrent iterations ----
    for (int t = 0; t < NITER; t++) {
        k_syncA<<<64, 256>>>(decay_action, idx_al, idx_ar);
        k_qgemm<<<dim3(8, 8), 256>>>();
        k_attn<<<256, 256>>>();
        k_syngemm<<<dim3(64, 4), 256>>>(syn_w);
        k_glu_ln_trace<<<32, 512>>>(syn_ln_g, syn_ln_b, t);
        k_nlm<<<2048, 256>>>(tp1_b, tp2_b, t);
        k_syncO<<<64, 256>>>(decay_out, idx_ol, idx_or, dout, t);
        k_outgemm<<<dim3(4, 8), 256>>>(out_w, out_b);
        k_entropy<<<32, 256>>>(dout, t);
    }
}

// round 4
// speedup vs baseline: 1.1260x; 1.1260x over previous
#include <cuda_runtime.h>
#include <cuda_bf16.h>
#include <math.h>
#include <stdint.h>

#define BB 32
#define SEQ 256
#define NITER 25
#define DM 2048
#define DI 512
#define NS 512
#define MEMN 25
#define OD 1000
#define SYN_KC 16

// ----------------- static device scratch -----------------
__device__ float g_xT[BB * SEQ * 512];         // (b,s,c)
__device__ float g_kv[BB * SEQ * DI];          // (b,s,d) post-LN
__device__ float g_KV[BB * SEQ * 2 * DI];      // (b,s,[K|V])
__device__ float g_Wqq[NS * DI];               // q_w @ wq^T  [n][e]
__device__ float g_bqq[DI];
__device__ float g_aoT[DI * DI];               // attn_out_w^T
__device__ float g_Was[DI * 2 * DM];           // aoT @ syn_w_top [d][j]
__device__ float g_synb2[2 * DM];
__device__ float g_tp1wt[DM * MEMN * 128];     // [d][m*128+h]
__device__ float g_tp2wt[DM * 128];            // [d][h*2+o]
__device__ float g_act[BB * DM];
__device__ float g_trace[BB * DM * MEMN];      // ring on last dim
__device__ float g_daa[2][BB * NS];
__device__ float g_dba[2][BB * NS];
__device__ float g_dao[2][BB * NS];
__device__ float g_dbo[2][BB * NS];
__device__ float g_ra[NS];
__device__ float g_ro[NS];
__device__ float g_q[BB * DI];
__device__ float g_attn[BB * DI];
__device__ float g_synp[SYN_KC * BB * 2 * DM]; // split-K partials
__device__ float g_pred[BB * OD];

// ----------------- helpers -----------------
__device__ __forceinline__ float warpSum(float v) {
#pragma unroll
    for (int o = 16; o; o >>= 1) v += __shfl_down_sync(0xffffffffu, v, o);
    return v;
}
__device__ __forceinline__ float warpMax(float v) {
#pragma unroll
    for (int o = 16; o; o >>= 1) v = fmaxf(v, __shfl_down_sync(0xffffffffu, v, o));
    return v;
}
template<int NW>
__device__ __forceinline__ float blockSumAll(float v, volatile float* red) {
    float s = warpSum(v);
    __syncthreads();
    if ((threadIdx.x & 31) == 0) red[threadIdx.x >> 5] = s;
    __syncthreads();
    float t = 0.f;
#pragma unroll
    for (int i = 0; i < NW; i++) t += red[i];
    return t;
}
template<int NW>
__device__ __forceinline__ float blockMaxAll(float v, volatile float* red) {
    float s = warpMax(v);
    __syncthreads();
    if ((threadIdx.x & 31) == 0) red[threadIdx.x >> 5] = s;
    __syncthreads();
    float t = -3.4e38f;
#pragma unroll
    for (int i = 0; i < NW; i++) t = fmaxf(t, red[i]);
    return t;
}
__device__ __forceinline__ float sigm(float x) { return 1.f / (1.f + expf(-x)); }

// ----------------- generic transpose (batched 2D) -----------------
__global__ void k_transpose(const float* __restrict__ in, float* __restrict__ out,
                            int R, int Cc) {
    __shared__ float t[32][33];
    int b = blockIdx.z;
    int r0 = blockIdx.y * 32, c0 = blockIdx.x * 32;
    const float* ip = in + (size_t)b * R * Cc;
    float* op = out + (size_t)b * R * Cc;
#pragma unroll
    for (int i = threadIdx.y; i < 32; i += 8) {
        int r = r0 + i, c = c0 + threadIdx.x;
        if (r < R && c < Cc) t[i][threadIdx.x] = ip[(size_t)r * Cc + c];
    }
    __syncthreads();
#pragma unroll
    for (int i = threadIdx.y; i < 32; i += 8) {
        int c = c0 + i, r = r0 + threadIdx.x;
        if (c < Cc && r < R) op[(size_t)c * R + r] = t[threadIdx.x][i];
    }
}

// ----------------- big GEMM: 128x128 tile, 8x8/thread -----------------
// C(MxN) = A(MxK) * B + bias.  transB=0: B KxN;  transB=1: B NxK.
// M,N multiples of 128; K multiple of 16.
__global__ void __launch_bounds__(256) k_gemm128(
    const float* __restrict__ A, const float* __restrict__ Bm,
    const float* __restrict__ bias, float* __restrict__ Cm,
    int M, int N, int K, int ldc, int cofs, int transB) {
    __shared__ float As[16][132];
    __shared__ float Bs[16][132];
    int m0 = blockIdx.y * 128, n0 = blockIdx.x * 128;
    int tid = threadIdx.x;
    int tx = tid & 15, ty = tid >> 4;
    float acc[8][8] = {};
    for (int k0 = 0; k0 < K; k0 += 16) {
#pragma unroll
        for (int r = 0; r < 2; r++) {
            int idx = tid + r * 256;
            int m = idx >> 2;
            int k4 = (idx & 3) * 4;
            float4 v = *(const float4*)&A[(size_t)(m0 + m) * K + k0 + k4];
            As[k4 + 0][m] = v.x; As[k4 + 1][m] = v.y;
            As[k4 + 2][m] = v.z; As[k4 + 3][m] = v.w;
        }
        if (!transB) {
#pragma unroll
            for (int r = 0; r < 2; r++) {
                int idx = tid + r * 256;
                int k = idx >> 5;
                int n4 = (idx & 31) * 4;
                float4 v = *(const float4*)&Bm[(size_t)(k0 + k) * N + n0 + n4];
                *(float4*)&Bs[k][n4] = v;
            }
        } else {
#pragma unroll
            for (int r = 0; r < 2; r++) {
                int idx = tid + r * 256;
                int n = idx >> 2;
                int k4 = (idx & 3) * 4;
                float4 v = *(const float4*)&Bm[(size_t)(n0 + n) * K + k0 + k4];
                Bs[k4 + 0][n] = v.x; Bs[k4 + 1][n] = v.y;
                Bs[k4 + 2][n] = v.z; Bs[k4 + 3][n] = v.w;
            }
        }
        __syncthreads();
#pragma unroll
        for (int k = 0; k < 16; k++) {
            float a[8], b[8];
            *(float4*)(a)     = *(const float4*)&As[k][ty * 4];
            *(float4*)(a + 4) = *(const float4*)&As[k][64 + ty * 4];
            *(float4*)(b)     = *(const float4*)&Bs[k][tx * 4];
            *(float4*)(b + 4) = *(const float4*)&Bs[k][64 + tx * 4];
#pragma unroll
            for (int i = 0; i < 8; i++)
#pragma unroll
                for (int j = 0; j < 8; j++) acc[i][j] += a[i] * b[j];
        }
        __syncthreads();
    }
#pragma unroll
    for (int i = 0; i < 8; i++) {
        int m = m0 + ((i < 4) ? (ty * 4 + i) : (60 + ty * 4 + i));
#pragma unroll
        for (int h = 0; h < 2; h++) {
            int nb = n0 + h * 64 + tx * 4;
            float4 v;
            v.x = acc[i][h * 4 + 0] + (bias ? bias[nb + 0] : 0.f);
            v.y = acc[i][h * 4 + 1] + (bias ? bias[nb + 1] : 0.f);
            v.z = acc[i][h * 4 + 2] + (bias ? bias[nb + 2] : 0.f);
            v.w = acc[i][h * 4 + 3] + (bias ? bias[nb + 3] : 0.f);
            *(float4*)&Cm[(size_t)m * ldc + cofs + nb] = v;
        }
    }
}

// ----------------- small GEMM (64x64 tile) for Wqq fold -----------------
__global__ void __launch_bounds__(256) k_gemm64(
    const float* __restrict__ A, const float* __restrict__ Bm,
    const float* __restrict__ bias, float* __restrict__ Cm,
    int M, int N, int K, int ldc, int cofs, int transB) {
    __shared__ float As[16][65];
    __shared__ float Bs[16][65];
    int m0 = blockIdx.y * 64, n0 = blockIdx.x * 64;
    int tid = threadIdx.x;
    int tx = tid % 16, ty = tid / 16;
    float acc[4][4] = {};
    for (int k0 = 0; k0 < K; k0 += 16) {
#pragma unroll
        for (int p = 0; p < 4; p++) {
            int m = (tid / 16) + p * 16;
            int k = tid % 16;
            As[k][m] = A[(size_t)(m0 + m) * K + k0 + k];
        }
        if (!transB) {
#pragma unroll
            for (int p = 0; p < 4; p++) {
                int kk = tid / 64 + p * 4;
                int n = tid % 64;
                Bs[kk][n] = Bm[(size_t)(k0 + kk) * N + n0 + n];
            }
        } else {
#pragma unroll
            for (int p = 0; p < 4; p++) {
                int n = tid / 16 + p * 16;
                int kk = tid % 16;
                Bs[kk][n] = Bm[(size_t)(n0 + n) * K + k0 + kk];
            }
        }
        __syncthreads();
#pragma unroll
        for (int k = 0; k < 16; k++) {
            float a[4], b[4];
#pragma unroll
            for (int i = 0; i < 4; i++) a[i] = As[k][ty * 4 + i];
#pragma unroll
            for (int j = 0; j < 4; j++) b[j] = Bs[k][tx * 4 + j];
#pragma unroll
            for (int i = 0; i < 4; i++)
#pragma unroll
                for (int j = 0; j < 4; j++) acc[i][j] += a[i] * b[j];
        }
        __syncthreads();
    }
#pragma unroll
    for (int i = 0; i < 4; i++) {
        int m = m0 + ty * 4 + i;
#pragma unroll
        for (int j = 0; j < 4; j++) {
            int n = n0 + tx * 4 + j;
            Cm[(size_t)m * ldc + cofs + n] = acc[i][j] + (bias ? bias[n] : 0.f);
        }
    }
}

// ----------------- LN over rows of 512 (in-place) -----------------
__global__ void k_ln512(float* __restrict__ buf, const float* __restrict__ g,
                        const float* __restrict__ bb) {
    __shared__ float red[8];
    float* p = buf + (size_t)blockIdx.x * 512;
    int tid = threadIdx.x;
    float v0 = p[tid], v1 = p[tid + 256];
    float mean = blockSumAll<8>(v0 + v1, red) * (1.f / 512.f);
    float d0 = v0 - mean, d1 = v1 - mean;
    float var = blockSumAll<8>(d0 * d0 + d1 * d1, red) * (1.f / 512.f);
    float inv = rsqrtf(var + 1e-5f);
    p[tid] = d0 * inv * g[tid] + bb[tid];
    p[tid + 256] = d1 * inv * g[tid + 256] + bb[tid + 256];
}

// ----------------- small precomputes -----------------
__global__ void k_bqq(const float* __restrict__ qb, const float* __restrict__ aw,
                      const float* __restrict__ bq) {
    int e = blockIdx.x * 256 + threadIdx.x;
    float s = bq[e];
    for (int d = 0; d < 512; d++) s += qb[d] * aw[(size_t)e * 512 + d];
    g_bqq[e] = s;
}
__global__ void k_synb2(const float* __restrict__ aob, const float* __restrict__ syn_w,
                        const float* __restrict__ syn_b) {
    int j = blockIdx.x * 256 + threadIdx.x;
    float s = syn_b[j];
    for (int e = 0; e < 512; e++) s += aob[e] * syn_w[(size_t)e * 4096 + j];
    g_synb2[j] = s;
}

// ----------------- state init -----------------
__global__ void k_init_state(const float* __restrict__ sas, const float* __restrict__ st) {
    int i = blockIdx.x * 256 + threadIdx.x;  // B*DM
    int d = i & 2047;
    g_act[i] = sas[d];
#pragma unroll
    for (int s = 0; s < 25; s++) g_trace[(size_t)i * 25 + s] = st[d * 25 + s];
}
__global__ void k_init_sync(const float* __restrict__ sas, const int* __restrict__ ol,
                            const int* __restrict__ orr,
                            const float* __restrict__ da, const float* __restrict__ dc) {
    int i = blockIdx.x * 256 + threadIdx.x;  // B*NS
    int n = i & 511;
    g_daa[0][i] = 0.f;
    g_dba[0][i] = 0.f;
    g_dao[0][i] = sas[ol[n]] * sas[orr[n]];
    g_dbo[0][i] = 1.f;
    if (i < 512) {
        g_ra[i] = expf(-fminf(fmaxf(da[i], 0.f), 15.f));
        g_ro[i] = expf(-fminf(fmaxf(dc[i], 0.f), 15.f));
    }
}

// ----------------- per-iteration kernels -----------------
// fused syncA update + q GEMM (q = syncA @ Wqq + bqq)
__global__ void k_qgemm(const int* __restrict__ il, const int* __restrict__ ir, int p) {
    __shared__ float sa[4][512];
    int b0 = blockIdx.y * 4;
    int e = blockIdx.x * 64 + (threadIdx.x & 63);
    int bl = threadIdx.x >> 6;
    for (int i = threadIdx.x; i < 2048; i += 256) {
        int bloc = i >> 9, n = i & 511;
        int b = b0 + bloc;
        float ra = g_ra[n];
        float prod = g_act[b * 2048 + il[n]] * g_act[b * 2048 + ir[n]];
        float daa = ra * g_daa[p][b * 512 + n] + prod;
        float dba = ra * g_dba[p][b * 512 + n] + 1.f;
        if (blockIdx.x == 0) {
            g_daa[1 - p][b * 512 + n] = daa;
            g_dba[1 - p][b * 512 + n] = dba;
        }
        sa[bloc][n] = daa * rsqrtf(dba);
    }
    __syncthreads();
    float acc = g_bqq[e];
#pragma unroll 4
    for (int n = 0; n < 512; n++) acc += sa[bl][n] * g_Wqq[(size_t)n * 512 + e];
    g_q[(b0 + bl) * 512 + e] = acc;
}

__global__ void k_attn() {
    int b = blockIdx.x >> 3, h = blockIdx.x & 7;
    int tid = threadIdx.x;
    __shared__ float qv[64];
    __shared__ float p[256];
    __shared__ float red[8];
    __shared__ float av[4][64];
    if (tid < 64) qv[tid] = g_q[b * 512 + h * 64 + tid];
    __syncthreads();
    const float* Kp = g_KV + ((size_t)(b * 256 + tid)) * 1024 + h * 64;
    float sc = 0.f;
#pragma unroll
    for (int dd = 0; dd < 64; dd++) sc += qv[dd] * Kp[dd];
    sc *= 0.125f;
    float mall = blockMaxAll<8>(sc, red);
    float e = expf(sc - mall);
    float ssum = blockSumAll<8>(e, red);
    p[tid] = e / ssum;
    __syncthreads();
    int dd = tid & 63, scx = tid >> 6;
    const float* Vp = g_KV + ((size_t)(b * 256 + scx * 64)) * 1024 + 512 + h * 64 + dd;
    float acc = 0.f;
#pragma unroll 8
    for (int j = 0; j < 64; j++) acc += p[scx * 64 + j] * Vp[(size_t)j * 1024];
    av[scx][dd] = acc;
    __syncthreads();
    if (tid < 64)
        g_attn[b * 512 + h * 64 + tid] = av[0][tid] + av[1][tid] + av[2][tid] + av[3][tid];
}

// syn GEMM: (32 x 2560) @ (2560 x 4096), split-K x16.
// thread: 4 b x 8 n. A broadcast from smem, W streamed from L2.
__global__ void __launch_bounds__(256) k_syngemm(const float* __restrict__ syn_w) {
    int n0 = blockIdx.x * 256;  // 16 n-blocks
    int kc = blockIdx.y;        // 16 k-chunks of 160
    __shared__ float As[32][32];
    int tid = threadIdx.x;
    int nt = tid & 31, bt = tid >> 5;  // 32 n-threads x 8 b-groups(4 b)
    float acc[4][8] = {};
    for (int ks = 0; ks < 160; ks += 32) {
        int k0 = kc * 160 + ks;
        __syncthreads();
#pragma unroll
        for (int r = 0; r < 4; r++) {
            int idx = tid + r * 256;
            int kk = idx >> 5, b = idx & 31;
            int k = k0 + kk;
            As[kk][b] = (k < 512) ? g_attn[b * 512 + k] : g_act[b * 2048 + (k - 512)];
        }
        __syncthreads();
        const float* Wp = (k0 < 512) ? (g_Was + (size_t)k0 * 4096 + n0)
                                     : (syn_w + (size_t)k0 * 4096 + n0);
#pragma unroll 8
        for (int kk = 0; kk < 32; kk++) {
            float4 a = *(const float4*)&As[kk][bt * 4];
            float4 w0 = *(const float4*)&Wp[(size_t)kk * 4096 + nt * 4];
            float4 w1 = *(const float4*)&Wp[(size_t)kk * 4096 + 128 + nt * 4];
            float av[4] = {a.x, a.y, a.z, a.w};
            float wv[8] = {w0.x, w0.y, w0.z, w0.w, w1.x, w1.y, w1.z, w1.w};
#pragma unroll
            for (int bi = 0; bi < 4; bi++)
#pragma unroll
                for (int nj = 0; nj < 8; nj++) acc[bi][nj] += av[bi] * wv[nj];
        }
    }
#pragma unroll
    for (int bi = 0; bi < 4; bi++) {
        int b = bt * 4 + bi;
        float* dst = g_synp + ((size_t)kc * 32 + b) * 4096 + n0;
        *(float4*)&dst[nt * 4] = *(float4*)&acc[bi][0];
        *(float4*)&dst[128 + nt * 4] = *(float4*)&acc[bi][4];
    }
}

// reduce split-K + GLU + LN + write state into trace ring slot
__global__ void k_glu_ln_trace(const float* __restrict__ lng, const float* __restrict__ lnb,
                               int wslot) {
    int b = blockIdx.x, tid = threadIdx.x;  // 512 threads
    __shared__ float red[16];
    float v[4];
    float s = 0.f;
#pragma unroll
    for (int q = 0; q < 4; q++) {
        int jj = tid + q * 512;
        float a = g_synb2[jj], gg = g_synb2[jj + 2048];
#pragma unroll
        for (int c = 0; c < SYN_KC; c++) {
            a += g_synp[((size_t)c * 32 + b) * 4096 + jj];
            gg += g_synp[((size_t)c * 32 + b) * 4096 + jj + 2048];
        }
        v[q] = a * sigm(gg);
        s += v[q];
    }
    float mean = blockSumAll<16>(s, red) * (1.f / 2048.f);
    float s2 = 0.f;
#pragma unroll
    for (int q = 0; q < 4; q++) {
        float d = v[q] - mean;
        s2 += d * d;
    }
    float var = blockSumAll<16>(s2, red) * (1.f / 2048.f);
    float inv = rsqrtf(var + 1e-5f);
#pragma unroll
    for (int q = 0; q < 4; q++) {
        int jj = tid + q * 512;
        float st = (v[q] - mean) * inv * lng[jj] + lnb[jj];
        g_trace[((size_t)b * 2048 + jj) * 25 + wslot] = st;
    }
}

// fused per-neuron NLM: tp1 -> GLU -> tp2 -> GLU -> act
__global__ void __launch_bounds__(256) k_nlm(const float* __restrict__ tp1b,
                                             const float* __restrict__ tp2b, int wslot) {
    int d = blockIdx.x;
    __shared__ float w1s[3200];
    __shared__ float b1s[128];
    __shared__ float w2s[128];
    __shared__ float b2s[2];
    __shared__ float ts[32 * 25];
    __shared__ float red[8][32][2];
    int tid = threadIdx.x;
    {
        const float4* src = (const float4*)(g_tp1wt + (size_t)d * 3200);
        float4* dst = (float4*)w1s;
        for (int i = tid; i < 800; i += 256) dst[i] = src[i];
    }
    if (tid < 128) {
        b1s[tid] = tp1b[d * 128 + tid];
        w2s[tid] = g_tp2wt[d * 128 + tid];
    }
    if (tid < 2) b2s[tid] = tp2b[d * 2 + tid];
    for (int i = tid; i < 800; i += 256) {
        int b = i / 25, m = i % 25;
        int slot = wslot + 1 + m;
        if (slot >= 25) slot -= 25;
        ts[b * 25 + m] = g_trace[((size_t)b * 2048 + d) * 25 + slot];
    }
    __syncthreads();
    int lane = tid & 31;  // batch
    int wi = tid >> 5;    // h-group
    int h0 = wi * 8;
    float a[8] = {}, gg[8] = {};
#pragma unroll
    for (int m = 0; m < 25; m++) {
        float tr = ts[lane * 25 + m];
        float4 a0 = *(const float4*)&w1s[m * 128 + h0];
        float4 a1 = *(const float4*)&w1s[m * 128 + h0 + 4];
        float4 g0 = *(const float4*)&w1s[m * 128 + h0 + 64];
        float4 g1 = *(const float4*)&w1s[m * 128 + h0 + 68];
        a[0] += tr * a0.x; a[1] += tr * a0.y; a[2] += tr * a0.z; a[3] += tr * a0.w;
        a[4] += tr * a1.x; a[5] += tr * a1.y; a[6] += tr * a1.z; a[7] += tr * a1.w;
        gg[0] += tr * g0.x; gg[1] += tr * g0.y; gg[2] += tr * g0.z; gg[3] += tr * g0.w;
        gg[4] += tr * g1.x; gg[5] += tr * g1.y; gg[6] += tr * g1.z; gg[7] += tr * g1.w;
    }
    float p0 = 0.f, p1 = 0.f;
#pragma unroll
    for (int j = 0; j < 8; j++) {
        float hv = (a[j] + b1s[h0 + j]) * sigm(gg[j] + b1s[h0 + 64 + j]);
        p0 += hv * w2s[(h0 + j) * 2];
        p1 += hv * w2s[(h0 + j) * 2 + 1];
    }
    red[wi][lane][0] = p0;
    red[wi][lane][1] = p1;
    __syncthreads();
    if (wi == 0) {
        float z0 = b2s[0], z1 = b2s[1];
#pragma unroll
        for (int k = 0; k < 8; k++) {
            z0 += red[k][lane][0];
            z1 += red[k][lane][1];
        }
        g_act[(size_t)lane * 2048 + d] = z0 * sigm(z1);
    }
}

// fused syncO update + out GEMM
__global__ void k_outgemm(const float* __restrict__ out_w, const float* __restrict__ out_b,
                          const int* __restrict__ il, const int* __restrict__ ir,
                          float* __restrict__ dout, int t) {
    __shared__ float so[4][512];
    int b0 = blockIdx.y * 4;
    int p = t & 1;
    for (int i = threadIdx.x; i < 2048; i += 256) {
        int bloc = i >> 9, n = i & 511;
        int b = b0 + bloc;
        float ro = g_ro[n];
        float prod = g_act[b * 2048 + il[n]] * g_act[b * 2048 + ir[n]];
        float dao = ro * g_dao[p][b * 512 + n] + prod;
        float dbo = ro * g_dbo[p][b * 512 + n] + 1.f;
        float sov = dao * rsqrtf(dbo);
        if (blockIdx.x == 0) {
            g_dao[1 - p][b * 512 + n] = dao;
            g_dbo[1 - p][b * 512 + n] = dbo;
            if (t == 24) dout[800000 + 1600 + (size_t)b * 512 + n] = sov;
        }
        so[bloc][n] = sov;
    }
    __syncthreads();
    int o = blockIdx.x * 256 + threadIdx.x;
    if (o >= 1000) return;
    float a0 = 0.f, a1 = 0.f, a2 = 0.f, a3 = 0.f;
#pragma unroll 4
    for (int n = 0; n < 512; n++) {
        float w = out_w[(size_t)n * 1000 + o];
        a0 += so[0][n] * w;
        a1 += so[1][n] * w;
        a2 += so[2][n] * w;
        a3 += so[3][n] * w;
    }
    float ob = out_b[o];
    g_pred[(size_t)(b0 + 0) * 1000 + o] = a0 + ob;
    g_pred[(size_t)(b0 + 1) * 1000 + o] = a1 + ob;
    g_pred[(size_t)(b0 + 2) * 1000 + o] = a2 + ob;
    g_pred[(size_t)(b0 + 3) * 1000 + o] = a3 + ob;
}

__global__ void k_entropy(float* __restrict__ dout, int t) {
    int b = blockIdx.x, tid = threadIdx.x;
    __shared__ float red[8];
    float mx = -3.4e38f;
    for (int o = tid; o < 1000; o += 256) mx = fmaxf(mx, g_pred[b * 1000 + o]);
    mx = blockMaxAll<8>(mx, red);
    float s = 0.f;
    for (int o = tid; o < 1000; o += 256) s += expf(g_pred[b * 1000 + o] - mx);
    s = blockSumAll<8>(s, red);
    float lse = mx + logf(s);
    float s2 = 0.f;
    for (int o = tid; o < 1000; o += 256) {
        float pv = g_pred[b * 1000 + o];
        float v = pv - lse;
        s2 += expf(v) * v;
        dout[(size_t)b * 25000 + (size_t)o * 25 + t] = pv;
    }
    s2 = blockSumAll<8>(s2, red);
    if (tid == 0) {
        float ne = -s2 / logf(1000.f);
        dout[800000 + (size_t)b * 50 + t] = ne;
        dout[800000 + (size_t)b * 50 + 25 + t] = 1.f - ne;
    }
}

// ----------------- host launcher -----------------
extern "C" void kernel_launch(void* const* d_in, const int* in_sizes, int n_in,
                              void* d_out, int out_size) {
    const float* x = (const float*)d_in[0];
    const float* kv_w = (const float*)d_in[1];
    const float* kv_b = (const float*)d_in[2];
    const float* kv_ln_g = (const float*)d_in[3];
    const float* kv_ln_b = (const float*)d_in[4];
    const float* q_w = (const float*)d_in[5];
    const float* q_b = (const float*)d_in[6];
    const float* attn_in_w = (const float*)d_in[7];
    const float* attn_in_b = (const float*)d_in[8];
    const float* attn_out_w = (const float*)d_in[9];
    const float* attn_out_b = (const float*)d_in[10];
    const float* syn_w = (const float*)d_in[11];
    const float* syn_b = (const float*)d_in[12];
    const float* syn_ln_g = (const float*)d_in[13];
    const float* syn_ln_b = (const float*)d_in[14];
    const float* tp1_w = (const float*)d_in[15];
    const float* tp1_b = (const float*)d_in[16];
    const float* tp2_w = (const float*)d_in[17];
    const float* tp2_b = (const float*)d_in[18];
    const float* sas = (const float*)d_in[19];
    const float* start_trace = (const float*)d_in[20];
    const float* decay_action = (const float*)d_in[21];
    const float* decay_out = (const float*)d_in[22];
    const float* out_w = (const float*)d_in[23];
    const float* out_b = (const float*)d_in[24];
    const int* idx_al = (const int*)d_in[25];
    const int* idx_ar = (const int*)d_in[26];
    const int* idx_ol = (const int*)d_in[27];
    const int* idx_or = (const int*)d_in[28];
    float* dout = (float*)d_out;

    float *p_xT, *p_kv, *p_KV, *p_aoT, *p_Was, *p_Wqq, *p_tp1wt, *p_tp2wt;
    cudaGetSymbolAddress((void**)&p_xT, g_xT);
    cudaGetSymbolAddress((void**)&p_kv, g_kv);
    cudaGetSymbolAddress((void**)&p_KV, g_KV);
    cudaGetSymbolAddress((void**)&p_aoT, g_aoT);
    cudaGetSymbolAddress((void**)&p_Was, g_Was);
    cudaGetSymbolAddress((void**)&p_Wqq, g_Wqq);
    cudaGetSymbolAddress((void**)&p_tp1wt, g_tp1wt);
    cudaGetSymbolAddress((void**)&p_tp2wt, g_tp2wt);

    // ---- preamble ----
    k_transpose<<<dim3(8, 16, 32), dim3(32, 8)>>>(x, p_xT, 512, 256);
    k_gemm128<<<dim3(4, 64), 256>>>(p_xT, kv_w, kv_b, p_kv, 8192, 512, 512, 512, 0, 0);
    k_ln512<<<8192, 256>>>(p_kv, kv_ln_g, kv_ln_b);
    // K and V in one GEMM (wk/wv rows contiguous in attn_in_w)
    k_gemm128<<<dim3(8, 64), 256>>>(p_kv, attn_in_w + 512 * 512, attn_in_b + 512,
                                    p_KV, 8192, 1024, 512, 1024, 0, 1);
    k_transpose<<<dim3(16, 16, 1), dim3(32, 8)>>>(attn_out_w, p_aoT, 512, 512);
    k_gemm128<<<dim3(32, 4), 256>>>(p_aoT, syn_w, (const float*)nullptr, p_Was,
                                    512, 4096, 512, 4096, 0, 0);
    k_gemm64<<<dim3(8, 8), 256>>>(q_w, attn_in_w, (const float*)nullptr, p_Wqq,
                                  512, 512, 512, 512, 0, 1);
    k_bqq<<<2, 256>>>(q_b, attn_in_w, attn_in_b);
    k_synb2<<<16, 256>>>(attn_out_b, syn_w, syn_b);
    k_transpose<<<dim3(64, 100, 1), dim3(32, 8)>>>(tp1_w, p_tp1wt, 3200, 2048);
    k_transpose<<<dim3(64, 4, 1), dim3(32, 8)>>>(tp2_w, p_tp2wt, 128, 2048);
    k_init_state<<<256, 256>>>(sas, start_trace);
    k_init_sync<<<64, 256>>>(sas, idx_ol, idx_or, decay_action, decay_out);

    // ---- 25 recurrent iterations ----
    for (int t = 0; t < NITER; t++) {
        k_qgemm<<<dim3(8, 8), 256>>>(idx_al, idx_ar, t & 1);
        k_attn<<<256, 256>>>();
        k_syngemm<<<dim3(16, SYN_KC), 256>>>(syn_w);
        k_glu_ln_trace<<<32, 512>>>(syn_ln_g, syn_ln_b, t);
        k_nlm<<<2048, 256>>>(tp1_b, tp2_b, t);
        k_outgemm<<<dim3(4, 8), 256>>>(out_w, out_b, idx_ol, idx_or, dout, t);
        k_entropy<<<32, 256>>>(dout, t);
    }
}

// round 5
// speedup vs baseline: 1.5106x; 1.3416x over previous
#include <cuda_runtime.h>
#include <cuda_bf16.h>
#include <math.h>
#include <stdint.h>

#define NITER 25
#define SYN_KC 16

// ----------------- static device scratch -----------------
__device__ float g_kv[32 * 256 * 512];       // (b,s,d) post-LN
__device__ float g_KV[32 * 256 * 1024];      // (b,s,[K|V])
__device__ float g_WqqT[512 * 512];          // [e][n]  (= wq@q_w^T row-major by e)
__device__ float g_bqq[512];
__device__ float g_Was[512 * 4096];          // aoT @ syn_w_top [d][j]
__device__ float g_synb2[4096];
__device__ float g_tp1wt[2048 * 3200];       // [d][m*128+h]
__device__ float g_tp2wt[2048 * 128];        // [d][h*2+o]
__device__ float g_act[32 * 2048];
__device__ float g_trace[32 * 2048 * 25];    // ring on last dim
__device__ float g_daa[2][32 * 512];
__device__ float g_dba[2][32 * 512];
__device__ float g_dao[2][32 * 512];
__device__ float g_dbo[2][32 * 512];
__device__ float g_ra[512];
__device__ float g_ro[512];
__device__ float g_attn[32 * 512];
__device__ float g_synp[SYN_KC * 32 * 4096]; // split-K partials

// ----------------- helpers -----------------
__device__ __forceinline__ float warpSum(float v) {
#pragma unroll
    for (int o = 16; o; o >>= 1) v += __shfl_down_sync(0xffffffffu, v, o);
    return v;
}
__device__ __forceinline__ float warpMax(float v) {
#pragma unroll
    for (int o = 16; o; o >>= 1) v = fmaxf(v, __shfl_down_sync(0xffffffffu, v, o));
    return v;
}
template<int NW>
__device__ __forceinline__ float blockSumAll(float v, volatile float* red) {
    float s = warpSum(v);
    __syncthreads();
    if ((threadIdx.x & 31) == 0) red[threadIdx.x >> 5] = s;
    __syncthreads();
    float t = 0.f;
#pragma unroll
    for (int i = 0; i < NW; i++) t += red[i];
    return t;
}
template<int NW>
__device__ __forceinline__ float blockMaxAll(float v, volatile float* red) {
    float s = warpMax(v);
    __syncthreads();
    if ((threadIdx.x & 31) == 0) red[threadIdx.x >> 5] = s;
    __syncthreads();
    float t = -3.4e38f;
#pragma unroll
    for (int i = 0; i < NW; i++) t = fmaxf(t, red[i]);
    return t;
}
__device__ __forceinline__ float sigm(float x) { return 1.f / (1.f + expf(-x)); }

// ----------------- big GEMM: 128x128 tile, 8x8/thread -----------------
// C(MxN) = op(A) * op(B) + bias
// amode 0: A row-major [m][k] (lda=K)
// amode 1: A col-major  [k][m] (lda=M)   (i.e. logical A = stored^T)
// amode 2: A = x tensor (b,c,s): A[m][k] = x[(m>>8)*512*256 + k*256 + (m&255)]
// transB 0: B KxN row-major;  transB 1: B NxK row-major.
__global__ void __launch_bounds__(256) k_gemm128(
    const float* __restrict__ A, const float* __restrict__ Bm,
    const float* __restrict__ bias, float* __restrict__ Cm,
    int M, int N, int K, int ldc, int amode, int transB) {
    __shared__ float As[16][132];
    __shared__ float Bs[16][132];
    int m0 = blockIdx.y * 128, n0 = blockIdx.x * 128;
    int tid = threadIdx.x;
    int tx = tid & 15, ty = tid >> 4;
    float acc[8][8] = {};
    for (int k0 = 0; k0 < K; k0 += 16) {
        if (amode == 0) {
#pragma unroll
            for (int r = 0; r < 2; r++) {
                int idx = tid + r * 256;
                int m = idx >> 2;
                int k4 = (idx & 3) * 4;
                float4 v = *(const float4*)&A[(size_t)(m0 + m) * K + k0 + k4];
                As[k4 + 0][m] = v.x; As[k4 + 1][m] = v.y;
                As[k4 + 2][m] = v.z; As[k4 + 3][m] = v.w;
            }
        } else if (amode == 1) {
#pragma unroll
            for (int r = 0; r < 2; r++) {
                int idx = tid + r * 256;
                int k = idx >> 5;
                int m4 = (idx & 31) * 4;
                float4 v = *(const float4*)&A[(size_t)(k0 + k) * M + m0 + m4];
                As[k][m4 + 0] = v.x; As[k][m4 + 1] = v.y;
                As[k][m4 + 2] = v.z; As[k][m4 + 3] = v.w;
            }
        } else {
            int b0 = m0 >> 8, s0 = m0 & 255;
#pragma unroll
            for (int r = 0; r < 2; r++) {
                int idx = tid + r * 256;
                int k = idx >> 5;
                int m4 = (idx & 31) * 4;
                float4 v = *(const float4*)&A[(size_t)b0 * 131072 + (size_t)(k0 + k) * 256 + s0 + m4];
                As[k][m4 + 0] = v.x; As[k][m4 + 1] = v.y;
                As[k][m4 + 2] = v.z; As[k][m4 + 3] = v.w;
            }
        }
        if (!transB) {
#pragma unroll
            for (int r = 0; r < 2; r++) {
                int idx = tid + r * 256;
                int k = idx >> 5;
                int n4 = (idx & 31) * 4;
                float4 v = *(const float4*)&Bm[(size_t)(k0 + k) * N + n0 + n4];
                *(float4*)&Bs[k][n4] = v;
            }
        } else {
#pragma unroll
            for (int r = 0; r < 2; r++) {
                int idx = tid + r * 256;
                int n = idx >> 2;
                int k4 = (idx & 3) * 4;
                float4 v = *(const float4*)&Bm[(size_t)(n0 + n) * K + k0 + k4];
                Bs[k4 + 0][n] = v.x; Bs[k4 + 1][n] = v.y;
                Bs[k4 + 2][n] = v.z; Bs[k4 + 3][n] = v.w;
            }
        }
        __syncthreads();
#pragma unroll
        for (int k = 0; k < 16; k++) {
            float a[8], b[8];
            *(float4*)(a)     = *(const float4*)&As[k][ty * 4];
            *(float4*)(a + 4) = *(const float4*)&As[k][64 + ty * 4];
            *(float4*)(b)     = *(const float4*)&Bs[k][tx * 4];
            *(float4*)(b + 4) = *(const float4*)&Bs[k][64 + tx * 4];
#pragma unroll
            for (int i = 0; i < 8; i++)
#pragma unroll
                for (int j = 0; j < 8; j++) acc[i][j] += a[i] * b[j];
        }
        __syncthreads();
    }
#pragma unroll
    for (int i = 0; i < 8; i++) {
        int m = m0 + ((i < 4) ? (ty * 4 + i) : (60 + ty * 4 + i));
#pragma unroll
        for (int h = 0; h < 2; h++) {
            int nb = n0 + h * 64 + tx * 4;
            float4 v;
            v.x = acc[i][h * 4 + 0] + (bias ? bias[nb + 0] : 0.f);
            v.y = acc[i][h * 4 + 1] + (bias ? bias[nb + 1] : 0.f);
            v.z = acc[i][h * 4 + 2] + (bias ? bias[nb + 2] : 0.f);
            v.w = acc[i][h * 4 + 3] + (bias ? bias[nb + 3] : 0.f);
            *(float4*)&Cm[(size_t)m * ldc + nb] = v;
        }
    }
}

// ----------------- LN over rows of 512 (in-place) -----------------
__global__ void k_ln512(float* __restrict__ buf, const float* __restrict__ g,
                        const float* __restrict__ bb) {
    __shared__ float red[8];
    float* p = buf + (size_t)blockIdx.x * 512;
    int tid = threadIdx.x;
    float v0 = p[tid], v1 = p[tid + 256];
    float mean = blockSumAll<8>(v0 + v1, red) * (1.f / 512.f);
    float d0 = v0 - mean, d1 = v1 - mean;
    float var = blockSumAll<8>(d0 * d0 + d1 * d1, red) * (1.f / 512.f);
    float inv = rsqrtf(var + 1e-5f);
    p[tid] = d0 * inv * g[tid] + bb[tid];
    p[tid + 256] = d1 * inv * g[tid + 256] + bb[tid + 256];
}

// ----------------- misc init mega-kernel (block-range dispatch) -----------------
__device__ __forceinline__ void transpose_tile(const float* __restrict__ in,
                                               float* __restrict__ out,
                                               int R, int Cc, int tr, int tc) {
    __shared__ float t[32][33];
    int tid = threadIdx.x;
    int lx = tid & 31, ly = tid >> 5;
    int r0 = tr * 32, c0 = tc * 32;
#pragma unroll
    for (int i = ly; i < 32; i += 8)
        t[i][lx] = in[(size_t)(r0 + i) * Cc + c0 + lx];
    __syncthreads();
#pragma unroll
    for (int i = ly; i < 32; i += 8)
        out[(size_t)(c0 + i) * R + r0 + lx] = t[lx][i];
}

__global__ void __launch_bounds__(256) k_misc(
    const float* __restrict__ q_w, const float* __restrict__ q_b,
    const float* __restrict__ attn_in_w, const float* __restrict__ attn_in_b,
    const float* __restrict__ attn_out_b,
    const float* __restrict__ syn_w, const float* __restrict__ syn_b,
    const float* __restrict__ tp1_w, const float* __restrict__ tp2_w,
    const float* __restrict__ sas, const float* __restrict__ st,
    const int* __restrict__ ol, const int* __restrict__ orr,
    const float* __restrict__ da, const float* __restrict__ dco) {
    int blk = blockIdx.x;
    int tid = threadIdx.x;
    if (blk < 64) {
        // WqqT[e][n] = sum_d attn_in_w[e*512+d] * q_w[n*512+d]
        __shared__ float As[16][65];
        __shared__ float Bs[16][65];
        int m0 = (blk >> 3) * 64, n0 = (blk & 7) * 64;
        int tx = tid % 16, ty = tid / 16;
        float acc[4][4] = {};
        for (int k0 = 0; k0 < 512; k0 += 16) {
#pragma unroll
            for (int p = 0; p < 4; p++) {
                int m = ty + p * 16;
                As[tx][m] = attn_in_w[(size_t)(m0 + m) * 512 + k0 + tx];
                Bs[tx][m] = q_w[(size_t)(n0 + m) * 512 + k0 + tx];
            }
            __syncthreads();
#pragma unroll
            for (int k = 0; k < 16; k++) {
                float a[4], b[4];
#pragma unroll
                for (int i = 0; i < 4; i++) a[i] = As[k][ty * 4 + i];
#pragma unroll
                for (int j = 0; j < 4; j++) b[j] = Bs[k][tx * 4 + j];
#pragma unroll
                for (int i = 0; i < 4; i++)
#pragma unroll
                    for (int j = 0; j < 4; j++) acc[i][j] += a[i] * b[j];
            }
            __syncthreads();
        }
#pragma unroll
        for (int i = 0; i < 4; i++)
#pragma unroll
            for (int j = 0; j < 4; j++)
                g_WqqT[(size_t)(m0 + ty * 4 + i) * 512 + n0 + tx * 4 + j] = acc[i][j];
    } else if (blk < 6464) {
        int tIdx = blk - 64;                      // tp1: [3200][2048] -> [2048][3200]
        transpose_tile(tp1_w, g_tp1wt, 3200, 2048, tIdx / 64, tIdx % 64);
    } else if (blk < 6720) {
        int tIdx = blk - 6464;                    // tp2: [128][2048] -> [2048][128]
        transpose_tile(tp2_w, g_tp2wt, 128, 2048, tIdx / 64, tIdx % 64);
    } else if (blk < 6722) {
        int e = (blk - 6720) * 256 + tid;
        float s = q_b ? 0.f : 0.f;
        s = attn_in_b[e];
        for (int d = 0; d < 512; d++) s += q_b[d] * attn_in_w[(size_t)e * 512 + d];
        g_bqq[e] = s;
    } else if (blk < 6738) {
        int j = (blk - 6722) * 256 + tid;
        float s = syn_b[j];
        for (int e = 0; e < 512; e++) s += attn_out_b[e] * syn_w[(size_t)e * 4096 + j];
        g_synb2[j] = s;
    } else if (blk < 6994) {
        int i = (blk - 6738) * 256 + tid;         // B*DM
        int d = i & 2047;
        g_act[i] = sas[d];
#pragma unroll
        for (int s = 0; s < 25; s++) g_trace[(size_t)i * 25 + s] = st[d * 25 + s];
    } else {
        int i = (blk - 6994) * 256 + tid;         // B*NS
        int n = i & 511;
        g_daa[0][i] = 0.f;
        g_dba[0][i] = 0.f;
        g_dao[0][i] = sas[ol[n]] * sas[orr[n]];
        g_dbo[0][i] = 1.f;
        if (i < 512) {
            g_ra[i] = expf(-fminf(fmaxf(da[i], 0.f), 15.f));
            g_ro[i] = expf(-fminf(fmaxf(dco[i], 0.f), 15.f));
        }
    }
}

// ----------------- loop phase 1: syncA + q + attention (fused) -----------------
// grid: 256 blocks = (b,h); 256 threads
__global__ void __launch_bounds__(256) k_phase1(const int* __restrict__ il,
                                                const int* __restrict__ ir, int p) {
    int b = blockIdx.x >> 3, h = blockIdx.x & 7;
    __shared__ float sa[512];
    __shared__ float qh[64];
    __shared__ float pr[256];
    __shared__ float red[8];
    __shared__ float av[4][64];
    int tid = threadIdx.x;
#pragma unroll
    for (int r = 0; r < 2; r++) {
        int n = tid + r * 256;
        float ra = g_ra[n];
        float prod = g_act[b * 2048 + il[n]] * g_act[b * 2048 + ir[n]];
        float daa = ra * g_daa[p][b * 512 + n] + prod;
        float dba = ra * g_dba[p][b * 512 + n] + 1.f;
        if (h == 0) {
            g_daa[1 - p][b * 512 + n] = daa;
            g_dba[1 - p][b * 512 + n] = dba;
        }
        sa[n] = daa * rsqrtf(dba);
    }
    __syncthreads();
    {   // q[h*64+e] = bqq + sum_n sa[n] * WqqT[h*64+e][n]  (4 threads per e)
        int e = tid >> 2, qd = tid & 3;
        const float* wr = g_WqqT + (size_t)(h * 64 + e) * 512 + qd * 128;
        const float* sap = sa + qd * 128;
        float acc = 0.f;
#pragma unroll
        for (int k = 0; k < 128; k += 4) {
            float4 w = *(const float4*)&wr[k];
            acc += sap[k] * w.x + sap[k + 1] * w.y + sap[k + 2] * w.z + sap[k + 3] * w.w;
        }
        acc += __shfl_down_sync(0xffffffffu, acc, 2);
        acc += __shfl_down_sync(0xffffffffu, acc, 1);
        if (qd == 0) qh[e] = acc + g_bqq[h * 64 + e];
    }
    __syncthreads();
    // scores over 256 tokens
    const float* Kp = g_KV + ((size_t)(b * 256 + tid)) * 1024 + h * 64;
    float sc = 0.f;
#pragma unroll
    for (int d4 = 0; d4 < 64; d4 += 4) {
        float4 kvv = *(const float4*)&Kp[d4];
        sc += qh[d4] * kvv.x + qh[d4 + 1] * kvv.y + qh[d4 + 2] * kvv.z + qh[d4 + 3] * kvv.w;
    }
    sc *= 0.125f;
    float mall = blockMaxAll<8>(sc, red);
    float e1 = expf(sc - mall);
    float ssum = blockSumAll<8>(e1, red);
    pr[tid] = e1 / ssum;
    __syncthreads();
    int dd = tid & 63, qq = tid >> 6;
    const float* Vp = g_KV + ((size_t)(b * 256 + qq * 64)) * 1024 + 512 + h * 64 + dd;
    float acc = 0.f;
#pragma unroll 8
    for (int j = 0; j < 64; j++) acc += pr[qq * 64 + j] * Vp[(size_t)j * 1024];
    av[qq][dd] = acc;
    __syncthreads();
    if (tid < 64)
        g_attn[b * 512 + h * 64 + tid] = av[0][tid] + av[1][tid] + av[2][tid] + av[3][tid];
}

// ----------------- loop phase 2: syn GEMM, split-K x16 -----------------
__global__ void __launch_bounds__(256) k_syngemm(const float* __restrict__ syn_w) {
    int n0 = blockIdx.x * 256;
    int kc = blockIdx.y;
    __shared__ float As[32][32];
    int tid = threadIdx.x;
    int nt = tid & 31, bt = tid >> 5;
    float acc[4][8] = {};
    for (int ks = 0; ks < 160; ks += 32) {
        int k0 = kc * 160 + ks;
        __syncthreads();
#pragma unroll
        for (int r = 0; r < 4; r++) {
            int idx = tid + r * 256;
            int kk = idx >> 5, b = idx & 31;
            int k = k0 + kk;
            As[kk][b] = (k < 512) ? g_attn[b * 512 + k] : g_act[b * 2048 + (k - 512)];
        }
        __syncthreads();
        const float* Wp = (k0 < 512) ? (g_Was + (size_t)k0 * 4096 + n0)
                                     : (syn_w + (size_t)k0 * 4096 + n0);
#pragma unroll 8
        for (int kk = 0; kk < 32; kk++) {
            float4 a = *(const float4*)&As[kk][bt * 4];
            float4 w0 = *(const float4*)&Wp[(size_t)kk * 4096 + nt * 4];
            float4 w1 = *(const float4*)&Wp[(size_t)kk * 4096 + 128 + nt * 4];
            float avv[4] = {a.x, a.y, a.z, a.w};
            float wv[8] = {w0.x, w0.y, w0.z, w0.w, w1.x, w1.y, w1.z, w1.w};
#pragma unroll
            for (int bi = 0; bi < 4; bi++)
#pragma unroll
                for (int nj = 0; nj < 8; nj++) acc[bi][nj] += avv[bi] * wv[nj];
        }
    }
#pragma unroll
    for (int bi = 0; bi < 4; bi++) {
        int b = bt * 4 + bi;
        float* dst = g_synp + ((size_t)kc * 32 + b) * 4096 + n0;
        *(float4*)&dst[nt * 4] = *(float4*)&acc[bi][0];
        *(float4*)&dst[128 + nt * 4] = *(float4*)&acc[bi][4];
    }
}

// ----------------- loop phase 3: reduce + GLU + LN + trace -----------------
__global__ void __launch_bounds__(1024) k_phase3(const float* __restrict__ lng,
                                                 const float* __restrict__ lnb, int wslot) {
    int b = blockIdx.x, tid = threadIdx.x;
    __shared__ float red[32];
    float v[2];
    float s = 0.f;
#pragma unroll
    for (int q = 0; q < 2; q++) {
        int jj = tid + q * 1024;
        float a = g_synb2[jj], gg = g_synb2[jj + 2048];
#pragma unroll
        for (int c = 0; c < SYN_KC; c++) {
            a += g_synp[((size_t)c * 32 + b) * 4096 + jj];
            gg += g_synp[((size_t)c * 32 + b) * 4096 + jj + 2048];
        }
        v[q] = a * sigm(gg);
        s += v[q];
    }
    float mean = blockSumAll<32>(s, red) * (1.f / 2048.f);
    float s2 = 0.f;
#pragma unroll
    for (int q = 0; q < 2; q++) {
        float d = v[q] - mean;
        s2 += d * d;
    }
    float var = blockSumAll<32>(s2, red) * (1.f / 2048.f);
    float inv = rsqrtf(var + 1e-5f);
#pragma unroll
    for (int q = 0; q < 2; q++) {
        int jj = tid + q * 1024;
        float st = (v[q] - mean) * inv * lng[jj] + lnb[jj];
        g_trace[((size_t)b * 2048 + jj) * 25 + wslot] = st;
    }
}

// ----------------- loop phase 4: per-neuron NLM -----------------
__global__ void __launch_bounds__(256) k_nlm(const float* __restrict__ tp1b,
                                             const float* __restrict__ tp2b, int wslot) {
    int d = blockIdx.x;
    __shared__ float w1s[3200];
    __shared__ float b1s[128];
    __shared__ float w2s[128];
    __shared__ float b2s[2];
    __shared__ float ts[32 * 25];
    __shared__ float red[8][32][2];
    int tid = threadIdx.x;
    {
        const float4* src = (const float4*)(g_tp1wt + (size_t)d * 3200);
        float4* dst = (float4*)w1s;
        for (int i = tid; i < 800; i += 256) dst[i] = src[i];
    }
    if (tid < 128) {
        b1s[tid] = tp1b[d * 128 + tid];
        w2s[tid] = g_tp2wt[d * 128 + tid];
    }
    if (tid < 2) b2s[tid] = tp2b[d * 2 + tid];
    for (int i = tid; i < 800; i += 256) {
        int b = i / 25, m = i % 25;
        int slot = wslot + 1 + m;
        if (slot >= 25) slot -= 25;
        ts[b * 25 + m] = g_trace[((size_t)b * 2048 + d) * 25 + slot];
    }
    __syncthreads();
    int lane = tid & 31;
    int wi = tid >> 5;
    int h0 = wi * 8;
    float a[8] = {}, gg[8] = {};
#pragma unroll
    for (int m = 0; m < 25; m++) {
        float tr = ts[lane * 25 + m];
        float4 a0 = *(const float4*)&w1s[m * 128 + h0];
        float4 a1 = *(const float4*)&w1s[m * 128 + h0 + 4];
        float4 g0 = *(const float4*)&w1s[m * 128 + h0 + 64];
        float4 g1 = *(const float4*)&w1s[m * 128 + h0 + 68];
        a[0] += tr * a0.x; a[1] += tr * a0.y; a[2] += tr * a0.z; a[3] += tr * a0.w;
        a[4] += tr * a1.x; a[5] += tr * a1.y; a[6] += tr * a1.z; a[7] += tr * a1.w;
        gg[0] += tr * g0.x; gg[1] += tr * g0.y; gg[2] += tr * g0.z; gg[3] += tr * g0.w;
        gg[4] += tr * g1.x; gg[5] += tr * g1.y; gg[6] += tr * g1.z; gg[7] += tr * g1.w;
    }
    float p0 = 0.f, p1 = 0.f;
#pragma unroll
    for (int j = 0; j < 8; j++) {
        float hv = (a[j] + b1s[h0 + j]) * sigm(gg[j] + b1s[h0 + 64 + j]);
        p0 += hv * w2s[(h0 + j) * 2];
        p1 += hv * w2s[(h0 + j) * 2 + 1];
    }
    red[wi][lane][0] = p0;
    red[wi][lane][1] = p1;
    __syncthreads();
    if (wi == 0) {
        float z0 = b2s[0], z1 = b2s[1];
#pragma unroll
        for (int k = 0; k < 8; k++) {
            z0 += red[k][lane][0];
            z1 += red[k][lane][1];
        }
        g_act[(size_t)lane * 2048 + d] = z0 * sigm(z1);
    }
}

// ----------------- loop phase 5: syncO + out GEMM + entropy (fused) -----------------
// grid: 32 blocks (b); 1024 threads
__global__ void __launch_bounds__(1024) k_phase5(
    const float* __restrict__ out_w, const float* __restrict__ out_b,
    const int* __restrict__ il, const int* __restrict__ ir,
    float* __restrict__ dout, int t) {
    int b = blockIdx.x;
    int tid = threadIdx.x;
    __shared__ float so[512];
    __shared__ float red[32];
    int p = t & 1;
    if (tid < 512) {
        int n = tid;
        float ro = g_ro[n];
        float prod = g_act[b * 2048 + il[n]] * g_act[b * 2048 + ir[n]];
        float dao = ro * g_dao[p][b * 512 + n] + prod;
        float dbo = ro * g_dbo[p][b * 512 + n] + 1.f;
        g_dao[1 - p][b * 512 + n] = dao;
        g_dbo[1 - p][b * 512 + n] = dbo;
        float sov = dao * rsqrtf(dbo);
        so[n] = sov;
        if (t == 24) dout[800000 + 1600 + (size_t)b * 512 + n] = sov;
    }
    __syncthreads();
    float pv = -3.4e38f;
    if (tid < 1000) {
        float acc = out_b[tid];
#pragma unroll 4
        for (int n = 0; n < 512; n++) acc += so[n] * out_w[(size_t)n * 1000 + tid];
        pv = acc;
    }
    float mall = blockMaxAll<32>(pv, red);
    float ex = (tid < 1000) ? expf(pv - mall) : 0.f;
    float ssum = blockSumAll<32>(ex, red);
    float lse = mall + logf(ssum);
    float contrib = (tid < 1000) ? expf(pv - lse) * (pv - lse) : 0.f;
    float s2 = blockSumAll<32>(contrib, red);
    if (tid < 1000) dout[(size_t)b * 25000 + (size_t)tid * 25 + t] = pv;
    if (tid == 0) {
        float ne = -s2 / logf(1000.f);
        dout[800000 + (size_t)b * 50 + t] = ne;
        dout[800000 + (size_t)b * 50 + 25 + t] = 1.f - ne;
    }
}

// ----------------- host launcher -----------------
extern "C" void kernel_launch(void* const* d_in, const int* in_sizes, int n_in,
                              void* d_out, int out_size) {
    const float* x = (const float*)d_in[0];
    const float* kv_w = (const float*)d_in[1];
    const float* kv_b = (const float*)d_in[2];
    const float* kv_ln_g = (const float*)d_in[3];
    const float* kv_ln_b = (const float*)d_in[4];
    const float* q_w = (const float*)d_in[5];
    const float* q_b = (const float*)d_in[6];
    const float* attn_in_w = (const float*)d_in[7];
    const float* attn_in_b = (const float*)d_in[8];
    const float* attn_out_w = (const float*)d_in[9];
    const float* attn_out_b = (const float*)d_in[10];
    const float* syn_w = (const float*)d_in[11];
    const float* syn_b = (const float*)d_in[12];
    const float* syn_ln_g = (const float*)d_in[13];
    const float* syn_ln_b = (const float*)d_in[14];
    const float* tp1_w = (const float*)d_in[15];
    const float* tp1_b = (const float*)d_in[16];
    const float* tp2_w = (const float*)d_in[17];
    const float* tp2_b = (const float*)d_in[18];
    const float* sas = (const float*)d_in[19];
    const float* start_trace = (const float*)d_in[20];
    const float* decay_action = (const float*)d_in[21];
    const float* decay_out = (const float*)d_in[22];
    const float* out_w = (const float*)d_in[23];
    const float* out_b = (const float*)d_in[24];
    const int* idx_al = (const int*)d_in[25];
    const int* idx_ar = (const int*)d_in[26];
    const int* idx_ol = (const int*)d_in[27];
    const int* idx_or = (const int*)d_in[28];
    float* dout = (float*)d_out;

    float *p_kv, *p_KV, *p_Was;
    cudaGetSymbolAddress((void**)&p_kv, g_kv);
    cudaGetSymbolAddress((void**)&p_KV, g_KV);
    cudaGetSymbolAddress((void**)&p_Was, g_Was);

    // ---- preamble: 5 nodes ----
    k_gemm128<<<dim3(4, 64), 256>>>(x, kv_w, kv_b, p_kv, 8192, 512, 512, 512, 2, 0);
    k_ln512<<<8192, 256>>>(p_kv, kv_ln_g, kv_ln_b);
    k_gemm128<<<dim3(8, 64), 256>>>(p_kv, attn_in_w + 512 * 512, attn_in_b + 512,
                                    p_KV, 8192, 1024, 512, 1024, 0, 1);
    k_gemm128<<<dim3(32, 4), 256>>>(attn_out_w, syn_w, (const float*)nullptr, p_Was,
                                    512, 4096, 512, 4096, 1, 0);
    k_misc<<<7058, 256>>>(q_w, q_b, attn_in_w, attn_in_b, attn_out_b, syn_w, syn_b,
                          tp1_w, tp2_w, sas, start_trace, idx_ol, idx_or,
                          decay_action, decay_out);

    // ---- 25 recurrent iterations: 5 nodes each ----
    for (int t = 0; t < NITER; t++) {
        k_phase1<<<256, 256>>>(idx_al, idx_ar, t & 1);
        k_syngemm<<<dim3(16, SYN_KC), 256>>>(syn_w);
        k_phase3<<<32, 1024>>>(syn_ln_g, syn_ln_b, t);
        k_nlm<<<2048, 256>>>(tp1_b, tp2_b, t);
        k_phase5<<<32, 1024>>>(out_w, out_b, idx_ol, idx_or, dout, t);
    }
}

// round 6
// speedup vs baseline: 2.1862x; 1.4472x over previous
#include <cuda_runtime.h>
#include <cuda_bf16.h>
#include <math.h>
#include <stdint.h>

#define NITER 25
#define SYN_KC 16

// ----------------- static device scratch -----------------
__device__ float g_kv[32 * 256 * 512];       // (b,s,d) post-LN
__device__ float g_KV[32 * 256 * 1024];      // (b,s,[K|V])
__device__ float g_WqqT[512 * 512];          // [e][n]
__device__ float g_bqq[512];
__device__ float g_Was[512 * 4096];          // aoT @ syn_w_top [d][j]
__device__ float g_synb2[4096];
__device__ float g_tp1wt[2048 * 3200];       // [d][m*128+h]
__device__ float g_tp2wt[2048 * 128];        // [d][h*2+o]
__device__ float g_act[2][32 * 2048];        // double-buffered (parity = t&1 written by nlm)
__device__ float g_trace[32 * 2048 * 25];    // ring on last dim
__device__ float g_daa[2][32 * 512];
__device__ float g_dba[2][32 * 512];
__device__ float g_dao[2][32 * 512];
__device__ float g_dbo[2][32 * 512];
__device__ float g_ra[512];
__device__ float g_ro[512];
__device__ float g_attn[32 * 512];
__device__ float g_synp[SYN_KC * 32 * 4096]; // split-K partials
__device__ float g_pred[32 * 1000];

// ----------------- helpers -----------------
__device__ __forceinline__ float warpSum(float v) {
#pragma unroll
    for (int o = 16; o; o >>= 1) v += __shfl_down_sync(0xffffffffu, v, o);
    return v;
}
__device__ __forceinline__ float warpMax(float v) {
#pragma unroll
    for (int o = 16; o; o >>= 1) v = fmaxf(v, __shfl_down_sync(0xffffffffu, v, o));
    return v;
}
template<int NW>
__device__ __forceinline__ float blockSumAll(float v, volatile float* red) {
    float s = warpSum(v);
    __syncthreads();
    if ((threadIdx.x & 31) == 0) red[threadIdx.x >> 5] = s;
    __syncthreads();
    float t = 0.f;
#pragma unroll
    for (int i = 0; i < NW; i++) t += red[i];
    return t;
}
template<int NW>
__device__ __forceinline__ float blockMaxAll(float v, volatile float* red) {
    float s = warpMax(v);
    __syncthreads();
    if ((threadIdx.x & 31) == 0) red[threadIdx.x >> 5] = s;
    __syncthreads();
    float t = -3.4e38f;
#pragma unroll
    for (int i = 0; i < NW; i++) t = fmaxf(t, red[i]);
    return t;
}
__device__ __forceinline__ float sigm(float x) { return 1.f / (1.f + expf(-x)); }

// ----------------- big GEMM: 128x128 tile, 8x8/thread -----------------
// amode 0: A row-major [m][k]; amode 1: A col-major [k][m];
// amode 2: A = x tensor (b,c,s): A[m][k] = x[(m>>8)*131072 + k*256 + (m&255)]
// transB 0: B KxN row-major;  transB 1: B NxK row-major.
__global__ void __launch_bounds__(256) k_gemm128(
    const float* __restrict__ A, const float* __restrict__ Bm,
    const float* __restrict__ bias, float* __restrict__ Cm,
    int M, int N, int K, int ldc, int amode, int transB) {
    __shared__ float As[16][132];
    __shared__ float Bs[16][132];
    int m0 = blockIdx.y * 128, n0 = blockIdx.x * 128;
    int tid = threadIdx.x;
    int tx = tid & 15, ty = tid >> 4;
    float acc[8][8] = {};
    for (int k0 = 0; k0 < K; k0 += 16) {
        if (amode == 0) {
#pragma unroll
            for (int r = 0; r < 2; r++) {
                int idx = tid + r * 256;
                int m = idx >> 2;
                int k4 = (idx & 3) * 4;
                float4 v = *(const float4*)&A[(size_t)(m0 + m) * K + k0 + k4];
                As[k4 + 0][m] = v.x; As[k4 + 1][m] = v.y;
                As[k4 + 2][m] = v.z; As[k4 + 3][m] = v.w;
            }
        } else if (amode == 1) {
#pragma unroll
            for (int r = 0; r < 2; r++) {
                int idx = tid + r * 256;
                int k = idx >> 5;
                int m4 = (idx & 31) * 4;
                float4 v = *(const float4*)&A[(size_t)(k0 + k) * M + m0 + m4];
                As[k][m4 + 0] = v.x; As[k][m4 + 1] = v.y;
                As[k][m4 + 2] = v.z; As[k][m4 + 3] = v.w;
            }
        } else {
            int b0 = m0 >> 8, s0 = m0 & 255;
#pragma unroll
            for (int r = 0; r < 2; r++) {
                int idx = tid + r * 256;
                int k = idx >> 5;
                int m4 = (idx & 31) * 4;
                float4 v = *(const float4*)&A[(size_t)b0 * 131072 + (size_t)(k0 + k) * 256 + s0 + m4];
                As[k][m4 + 0] = v.x; As[k][m4 + 1] = v.y;
                As[k][m4 + 2] = v.z; As[k][m4 + 3] = v.w;
            }
        }
        if (!transB) {
#pragma unroll
            for (int r = 0; r < 2; r++) {
                int idx = tid + r * 256;
                int k = idx >> 5;
                int n4 = (idx & 31) * 4;
                float4 v = *(const float4*)&Bm[(size_t)(k0 + k) * N + n0 + n4];
                *(float4*)&Bs[k][n4] = v;
            }
        } else {
#pragma unroll
            for (int r = 0; r < 2; r++) {
                int idx = tid + r * 256;
                int n = idx >> 2;
                int k4 = (idx & 3) * 4;
                float4 v = *(const float4*)&Bm[(size_t)(n0 + n) * K + k0 + k4];
                Bs[k4 + 0][n] = v.x; Bs[k4 + 1][n] = v.y;
                Bs[k4 + 2][n] = v.z; Bs[k4 + 3][n] = v.w;
            }
        }
        __syncthreads();
#pragma unroll
        for (int k = 0; k < 16; k++) {
            float a[8], b[8];
            *(float4*)(a)     = *(const float4*)&As[k][ty * 4];
            *(float4*)(a + 4) = *(const float4*)&As[k][64 + ty * 4];
            *(float4*)(b)     = *(const float4*)&Bs[k][tx * 4];
            *(float4*)(b + 4) = *(const float4*)&Bs[k][64 + tx * 4];
#pragma unroll
            for (int i = 0; i < 8; i++)
#pragma unroll
                for (int j = 0; j < 8; j++) acc[i][j] += a[i] * b[j];
        }
        __syncthreads();
    }
#pragma unroll
    for (int i = 0; i < 8; i++) {
        int m = m0 + ((i < 4) ? (ty * 4 + i) : (60 + ty * 4 + i));
#pragma unroll
        for (int h = 0; h < 2; h++) {
            int nb = n0 + h * 64 + tx * 4;
            float4 v;
            v.x = acc[i][h * 4 + 0] + (bias ? bias[nb + 0] : 0.f);
            v.y = acc[i][h * 4 + 1] + (bias ? bias[nb + 1] : 0.f);
            v.z = acc[i][h * 4 + 2] + (bias ? bias[nb + 2] : 0.f);
            v.w = acc[i][h * 4 + 3] + (bias ? bias[nb + 3] : 0.f);
            *(float4*)&Cm[(size_t)m * ldc + nb] = v;
        }
    }
}

// ----------------- LN over rows of 512 (in-place) -----------------
__global__ void k_ln512(float* __restrict__ buf, const float* __restrict__ g,
                        const float* __restrict__ bb) {
    __shared__ float red[8];
    float* p = buf + (size_t)blockIdx.x * 512;
    int tid = threadIdx.x;
    float v0 = p[tid], v1 = p[tid + 256];
    float mean = blockSumAll<8>(v0 + v1, red) * (1.f / 512.f);
    float d0 = v0 - mean, d1 = v1 - mean;
    float var = blockSumAll<8>(d0 * d0 + d1 * d1, red) * (1.f / 512.f);
    float inv = rsqrtf(var + 1e-5f);
    p[tid] = d0 * inv * g[tid] + bb[tid];
    p[tid + 256] = d1 * inv * g[tid + 256] + bb[tid + 256];
}

// ----------------- misc init mega-kernel -----------------
__device__ __forceinline__ void transpose_tile(const float* __restrict__ in,
                                               float* __restrict__ out,
                                               int R, int Cc, int tr, int tc) {
    __shared__ float t[32][33];
    int tid = threadIdx.x;
    int lx = tid & 31, ly = tid >> 5;
    int r0 = tr * 32, c0 = tc * 32;
#pragma unroll
    for (int i = ly; i < 32; i += 8)
        t[i][lx] = in[(size_t)(r0 + i) * Cc + c0 + lx];
    __syncthreads();
#pragma unroll
    for (int i = ly; i < 32; i += 8)
        out[(size_t)(c0 + i) * R + r0 + lx] = t[lx][i];
}

__global__ void __launch_bounds__(256) k_misc(
    const float* __restrict__ q_w, const float* __restrict__ q_b,
    const float* __restrict__ attn_in_w, const float* __restrict__ attn_in_b,
    const float* __restrict__ attn_out_b,
    const float* __restrict__ syn_w, const float* __restrict__ syn_b,
    const float* __restrict__ tp1_w, const float* __restrict__ tp2_w,
    const float* __restrict__ sas, const float* __restrict__ st,
    const int* __restrict__ ol, const int* __restrict__ orr,
    const float* __restrict__ da, const float* __restrict__ dco) {
    int blk = blockIdx.x;
    int tid = threadIdx.x;
    if (blk < 64) {
        __shared__ float As[16][65];
        __shared__ float Bs[16][65];
        int m0 = (blk >> 3) * 64, n0 = (blk & 7) * 64;
        int tx = tid % 16, ty = tid / 16;
        float acc[4][4] = {};
        for (int k0 = 0; k0 < 512; k0 += 16) {
#pragma unroll
            for (int p = 0; p < 4; p++) {
                int m = ty + p * 16;
                As[tx][m] = attn_in_w[(size_t)(m0 + m) * 512 + k0 + tx];
                Bs[tx][m] = q_w[(size_t)(n0 + m) * 512 + k0 + tx];
            }
            __syncthreads();
#pragma unroll
            for (int k = 0; k < 16; k++) {
                float a[4], b[4];
#pragma unroll
                for (int i = 0; i < 4; i++) a[i] = As[k][ty * 4 + i];
#pragma unroll
                for (int j = 0; j < 4; j++) b[j] = Bs[k][tx * 4 + j];
#pragma unroll
                for (int i = 0; i < 4; i++)
#pragma unroll
                    for (int j = 0; j < 4; j++) acc[i][j] += a[i] * b[j];
            }
            __syncthreads();
        }
#pragma unroll
        for (int i = 0; i < 4; i++)
#pragma unroll
            for (int j = 0; j < 4; j++)
                g_WqqT[(size_t)(m0 + ty * 4 + i) * 512 + n0 + tx * 4 + j] = acc[i][j];
    } else if (blk < 6464) {
        int tIdx = blk - 64;
        transpose_tile(tp1_w, g_tp1wt, 3200, 2048, tIdx / 64, tIdx % 64);
    } else if (blk < 6720) {
        int tIdx = blk - 6464;
        transpose_tile(tp2_w, g_tp2wt, 128, 2048, tIdx / 64, tIdx % 64);
    } else if (blk < 6722) {
        int e = (blk - 6720) * 256 + tid;
        float s = attn_in_b[e];
        for (int d = 0; d < 512; d++) s += q_b[d] * attn_in_w[(size_t)e * 512 + d];
        g_bqq[e] = s;
    } else if (blk < 6738) {
        int j = (blk - 6722) * 256 + tid;
        float s = syn_b[j];
        for (int e = 0; e < 512; e++) s += attn_out_b[e] * syn_w[(size_t)e * 4096 + j];
        g_synb2[j] = s;
    } else if (blk < 6994) {
        int i = (blk - 6738) * 256 + tid;
        int d = i & 2047;
        g_act[1][i] = sas[d];
#pragma unroll
        for (int s = 0; s < 25; s++) g_trace[(size_t)i * 25 + s] = st[d * 25 + s];
    } else {
        int i = (blk - 6994) * 256 + tid;
        int n = i & 511;
        g_daa[0][i] = 0.f;
        g_dba[0][i] = 0.f;
        g_dao[0][i] = sas[ol[n]] * sas[orr[n]];
        g_dbo[0][i] = 1.f;
        if (i < 512) {
            g_ra[i] = expf(-fminf(fmaxf(da[i], 0.f), 15.f));
            g_ro[i] = expf(-fminf(fmaxf(dco[i], 0.f), 15.f));
        }
    }
}

// ----------------- loop phase 1: syncA + q + attention -----------------
__global__ void __launch_bounds__(256) k_phase1(const int* __restrict__ il,
                                                const int* __restrict__ ir, int p) {
    int b = blockIdx.x >> 3, h = blockIdx.x & 7;
    __shared__ float sa[512];
    __shared__ float qh[64];
    __shared__ float pr[256];
    __shared__ float red[8];
    __shared__ float av[4][64];
    int tid = threadIdx.x;
    const float* act = g_act[1 - p];
#pragma unroll
    for (int r = 0; r < 2; r++) {
        int n = tid + r * 256;
        float ra = g_ra[n];
        float prod = act[b * 2048 + il[n]] * act[b * 2048 + ir[n]];
        float daa = ra * g_daa[p][b * 512 + n] + prod;
        float dba = ra * g_dba[p][b * 512 + n] + 1.f;
        if (h == 0) {
            g_daa[1 - p][b * 512 + n] = daa;
            g_dba[1 - p][b * 512 + n] = dba;
        }
        sa[n] = daa * rsqrtf(dba);
    }
    __syncthreads();
    {
        int e = tid >> 2, qd = tid & 3;
        const float* wr = g_WqqT + (size_t)(h * 64 + e) * 512 + qd * 128;
        const float* sap = sa + qd * 128;
        float acc = 0.f;
#pragma unroll
        for (int k = 0; k < 128; k += 4) {
            float4 w = *(const float4*)&wr[k];
            acc += sap[k] * w.x + sap[k + 1] * w.y + sap[k + 2] * w.z + sap[k + 3] * w.w;
        }
        acc += __shfl_down_sync(0xffffffffu, acc, 2);
        acc += __shfl_down_sync(0xffffffffu, acc, 1);
        if (qd == 0) qh[e] = acc + g_bqq[h * 64 + e];
    }
    __syncthreads();
    const float* Kp = g_KV + ((size_t)(b * 256 + tid)) * 1024 + h * 64;
    float sc = 0.f;
#pragma unroll
    for (int d4 = 0; d4 < 64; d4 += 4) {
        float4 kvv = *(const float4*)&Kp[d4];
        sc += qh[d4] * kvv.x + qh[d4 + 1] * kvv.y + qh[d4 + 2] * kvv.z + qh[d4 + 3] * kvv.w;
    }
    sc *= 0.125f;
    float mall = blockMaxAll<8>(sc, red);
    float e1 = expf(sc - mall);
    float ssum = blockSumAll<8>(e1, red);
    pr[tid] = e1 / ssum;
    __syncthreads();
    int dd = tid & 63, qq = tid >> 6;
    const float* Vp = g_KV + ((size_t)(b * 256 + qq * 64)) * 1024 + 512 + h * 64 + dd;
    float acc = 0.f;
#pragma unroll 8
    for (int j = 0; j < 64; j++) acc += pr[qq * 64 + j] * Vp[(size_t)j * 1024];
    av[qq][dd] = acc;
    __syncthreads();
    if (tid < 64)
        g_attn[b * 512 + h * 64 + tid] = av[0][tid] + av[1][tid] + av[2][tid] + av[3][tid];
}

// ----------------- loop phase 2: syn GEMM, split-K x16, n-tile 128 -----------------
__global__ void __launch_bounds__(256) k_syngemm(const float* __restrict__ syn_w, int p) {
    int n0 = blockIdx.x * 128;  // 32 n-blocks
    int kc = blockIdx.y;        // 16 k-chunks of 160
    __shared__ float As[32][32];
    int tid = threadIdx.x;
    int nt = tid & 31, bt = tid >> 5;
    const float* act = g_act[1 - p];
    float acc[4][4] = {};
    for (int ks = 0; ks < 160; ks += 32) {
        int k0 = kc * 160 + ks;
        __syncthreads();
#pragma unroll
        for (int r = 0; r < 4; r++) {
            int idx = tid + r * 256;
            int kk = idx >> 5, b = idx & 31;
            int k = k0 + kk;
            As[kk][b] = (k < 512) ? g_attn[b * 512 + k] : act[b * 2048 + (k - 512)];
        }
        __syncthreads();
        const float* Wp = (k0 < 512) ? (g_Was + (size_t)k0 * 4096 + n0)
                                     : (syn_w + (size_t)k0 * 4096 + n0);
#pragma unroll 8
        for (int kk = 0; kk < 32; kk++) {
            float4 a = *(const float4*)&As[kk][bt * 4];
            float4 w = *(const float4*)&Wp[(size_t)kk * 4096 + nt * 4];
            float avv[4] = {a.x, a.y, a.z, a.w};
            float wv[4] = {w.x, w.y, w.z, w.w};
#pragma unroll
            for (int bi = 0; bi < 4; bi++)
#pragma unroll
                for (int nj = 0; nj < 4; nj++) acc[bi][nj] += avv[bi] * wv[nj];
        }
    }
#pragma unroll
    for (int bi = 0; bi < 4; bi++) {
        int b = bt * 4 + bi;
        float* dst = g_synp + ((size_t)kc * 32 + b) * 4096 + n0;
        *(float4*)&dst[nt * 4] = *(float4*)&acc[bi][0];
    }
}

// ----------------- loop phase 3: reduce + GLU + LN + trace -----------------
__global__ void __launch_bounds__(1024) k_phase3(const float* __restrict__ lng,
                                                 const float* __restrict__ lnb, int wslot) {
    int b = blockIdx.x, tid = threadIdx.x;
    __shared__ float red[32];
    float v[2];
    float s = 0.f;
#pragma unroll
    for (int q = 0; q < 2; q++) {
        int jj = tid + q * 1024;
        float a = g_synb2[jj], gg = g_synb2[jj + 2048];
#pragma unroll
        for (int c = 0; c < SYN_KC; c++) {
            a += g_synp[((size_t)c * 32 + b) * 4096 + jj];
            gg += g_synp[((size_t)c * 32 + b) * 4096 + jj + 2048];
        }
        v[q] = a * sigm(gg);
        s += v[q];
    }
    float mean = blockSumAll<32>(s, red) * (1.f / 2048.f);
    float s2 = 0.f;
#pragma unroll
    for (int q = 0; q < 2; q++) {
        float d = v[q] - mean;
        s2 += d * d;
    }
    float var = blockSumAll<32>(s2, red) * (1.f / 2048.f);
    float inv = rsqrtf(var + 1e-5f);
#pragma unroll
    for (int q = 0; q < 2; q++) {
        int jj = tid + q * 1024;
        float st = (v[q] - mean) * inv * lng[jj] + lnb[jj];
        g_trace[((size_t)b * 2048 + jj) * 25 + wslot] = st;
    }
}

// ----------------- loop phase 4: per-neuron NLM -----------------
__global__ void __launch_bounds__(256) k_nlm(const float* __restrict__ tp1b,
                                             const float* __restrict__ tp2b,
                                             int wslot, int p) {
    int d = blockIdx.x;
    __shared__ float w1s[3200];
    __shared__ float b1s[128];
    __shared__ float w2s[128];
    __shared__ float b2s[2];
    __shared__ float ts[32 * 25];
    __shared__ float red[8][32][2];
    int tid = threadIdx.x;
    {
        const float4* src = (const float4*)(g_tp1wt + (size_t)d * 3200);
        float4* dst = (float4*)w1s;
        for (int i = tid; i < 800; i += 256) dst[i] = src[i];
    }
    if (tid < 128) {
        b1s[tid] = tp1b[d * 128 + tid];
        w2s[tid] = g_tp2wt[d * 128 + tid];
    }
    if (tid < 2) b2s[tid] = tp2b[d * 2 + tid];
    for (int i = tid; i < 800; i += 256) {
        int b = i / 25, m = i % 25;
        int slot = wslot + 1 + m;
        if (slot >= 25) slot -= 25;
        ts[b * 25 + m] = g_trace[((size_t)b * 2048 + d) * 25 + slot];
    }
    __syncthreads();
    int lane = tid & 31;
    int wi = tid >> 5;
    int h0 = wi * 8;
    float a[8] = {}, gg[8] = {};
#pragma unroll
    for (int m = 0; m < 25; m++) {
        float tr = ts[lane * 25 + m];
        float4 a0 = *(const float4*)&w1s[m * 128 + h0];
        float4 a1 = *(const float4*)&w1s[m * 128 + h0 + 4];
        float4 g0 = *(const float4*)&w1s[m * 128 + h0 + 64];
        float4 g1 = *(const float4*)&w1s[m * 128 + h0 + 68];
        a[0] += tr * a0.x; a[1] += tr * a0.y; a[2] += tr * a0.z; a[3] += tr * a0.w;
        a[4] += tr * a1.x; a[5] += tr * a1.y; a[6] += tr * a1.z; a[7] += tr * a1.w;
        gg[0] += tr * g0.x; gg[1] += tr * g0.y; gg[2] += tr * g0.z; gg[3] += tr * g0.w;
        gg[4] += tr * g1.x; gg[5] += tr * g1.y; gg[6] += tr * g1.z; gg[7] += tr * g1.w;
    }
    float p0 = 0.f, p1 = 0.f;
#pragma unroll
    for (int j = 0; j < 8; j++) {
        float hv = (a[j] + b1s[h0 + j]) * sigm(gg[j] + b1s[h0 + 64 + j]);
        p0 += hv * w2s[(h0 + j) * 2];
        p1 += hv * w2s[(h0 + j) * 2 + 1];
    }
    red[wi][lane][0] = p0;
    red[wi][lane][1] = p1;
    __syncthreads();
    if (wi == 0) {
        float z0 = b2s[0], z1 = b2s[1];
#pragma unroll
        for (int k = 0; k < 8; k++) {
            z0 += red[k][lane][0];
            z1 += red[k][lane][1];
        }
        g_act[p][(size_t)lane * 2048 + d] = z0 * sigm(z1);
    }
}

// ----------------- out branch: syncO + out GEMM (spread over o-chunks) -----------------
__global__ void __launch_bounds__(256) k_outgemm(
    const float* __restrict__ out_w, const float* __restrict__ out_b,
    const int* __restrict__ il, const int* __restrict__ ir,
    float* __restrict__ dout, int t) {
    int b = blockIdx.y, oc = blockIdx.x;
    int tid = threadIdx.x;
    __shared__ float so[512];
    int p = t & 1;
    const float* act = g_act[p];
    for (int i = tid; i < 512; i += 256) {
        int n = i;
        float ro = g_ro[n];
        float prod = act[b * 2048 + il[n]] * act[b * 2048 + ir[n]];
        float dao = ro * g_dao[p][b * 512 + n] + prod;
        float dbo = ro * g_dbo[p][b * 512 + n] + 1.f;
        float sov = dao * rsqrtf(dbo);
        if (oc == 0) {
            g_dao[1 - p][b * 512 + n] = dao;
            g_dbo[1 - p][b * 512 + n] = dbo;
            if (t == 24) dout[800000 + 1600 + (size_t)b * 512 + n] = sov;
        }
        so[n] = sov;
    }
    __syncthreads();
    if (tid < 250) {
        int o = oc * 250 + tid;
        float acc = out_b[o];
#pragma unroll 4
        for (int n = 0; n < 512; n++) acc += so[n] * out_w[(size_t)n * 1000 + o];
        g_pred[b * 1000 + o] = acc;
        dout[(size_t)b * 25000 + (size_t)o * 25 + t] = acc;
    }
}

__global__ void k_entropy(float* __restrict__ dout, int t) {
    int b = blockIdx.x, tid = threadIdx.x;
    __shared__ float red[8];
    float mx = -3.4e38f;
    for (int o = tid; o < 1000; o += 256) mx = fmaxf(mx, g_pred[b * 1000 + o]);
    mx = blockMaxAll<8>(mx, red);
    float s = 0.f;
    for (int o = tid; o < 1000; o += 256) s += expf(g_pred[b * 1000 + o] - mx);
    s = blockSumAll<8>(s, red);
    float lse = mx + logf(s);
    float s2 = 0.f;
    for (int o = tid; o < 1000; o += 256) {
        float v = g_pred[b * 1000 + o] - lse;
        s2 += expf(v) * v;
    }
    s2 = blockSumAll<8>(s2, red);
    if (tid == 0) {
        float ne = -s2 / logf(1000.f);
        dout[800000 + (size_t)b * 50 + t] = ne;
        dout[800000 + (size_t)b * 50 + 25 + t] = 1.f - ne;
    }
}

// ----------------- host launcher -----------------
extern "C" void kernel_launch(void* const* d_in, const int* in_sizes, int n_in,
                              void* d_out, int out_size) {
    const float* x = (const float*)d_in[0];
    const float* kv_w = (const float*)d_in[1];
    const float* kv_b = (const float*)d_in[2];
    const float* kv_ln_g = (const float*)d_in[3];
    const float* kv_ln_b = (const float*)d_in[4];
    const float* q_w = (const float*)d_in[5];
    const float* q_b = (const float*)d_in[6];
    const float* attn_in_w = (const float*)d_in[7];
    const float* attn_in_b = (const float*)d_in[8];
    const float* attn_out_w = (const float*)d_in[9];
    const float* attn_out_b = (const float*)d_in[10];
    const float* syn_w = (const float*)d_in[11];
    const float* syn_b = (const float*)d_in[12];
    const float* syn_ln_g = (const float*)d_in[13];
    const float* syn_ln_b = (const float*)d_in[14];
    const float* tp1_w = (const float*)d_in[15];
    const float* tp1_b = (const float*)d_in[16];
    const float* tp2_w = (const float*)d_in[17];
    const float* tp2_b = (const float*)d_in[18];
    const float* sas = (const float*)d_in[19];
    const float* start_trace = (const float*)d_in[20];
    const float* decay_action = (const float*)d_in[21];
    const float* decay_out = (const float*)d_in[22];
    const float* out_w = (const float*)d_in[23];
    const float* out_b = (const float*)d_in[24];
    const int* idx_al = (const int*)d_in[25];
    const int* idx_ar = (const int*)d_in[26];
    const int* idx_ol = (const int*)d_in[27];
    const int* idx_or = (const int*)d_in[28];
    float* dout = (float*)d_out;

    float *p_kv, *p_KV, *p_Was;
    cudaGetSymbolAddress((void**)&p_kv, g_kv);
    cudaGetSymbolAddress((void**)&p_KV, g_KV);
    cudaGetSymbolAddress((void**)&p_Was, g_Was);

    // lazily created side stream + reusable events (created on the eager
    // correctness call, before graph capture begins; reused inside capture)
    static cudaStream_t s2 = nullptr;
    static cudaEvent_t evF = nullptr, evP = nullptr, evI = nullptr, evJ = nullptr;
    if (!s2) {
        cudaStreamCreateWithFlags(&s2, cudaStreamNonBlocking);
        cudaEventCreateWithFlags(&evF, cudaEventDisableTiming);
        cudaEventCreateWithFlags(&evP, cudaEventDisableTiming);
        cudaEventCreateWithFlags(&evI, cudaEventDisableTiming);
        cudaEventCreateWithFlags(&evJ, cudaEventDisableTiming);
    }

    // ---- preamble: fork Was-fold + misc onto s2, kv chain on main ----
    cudaEventRecord(evF, 0);
    cudaStreamWaitEvent(s2, evF, 0);
    k_gemm128<<<dim3(32, 4), 256, 0, s2>>>(attn_out_w, syn_w, (const float*)nullptr,
                                           p_Was, 512, 4096, 512, 4096, 1, 0);
    k_misc<<<7058, 256, 0, s2>>>(q_w, q_b, attn_in_w, attn_in_b, attn_out_b, syn_w, syn_b,
                                 tp1_w, tp2_w, sas, start_trace, idx_ol, idx_or,
                                 decay_action, decay_out);
    cudaEventRecord(evP, s2);

    k_gemm128<<<dim3(4, 64), 256>>>(x, kv_w, kv_b, p_kv, 8192, 512, 512, 512, 2, 0);
    k_ln512<<<8192, 256>>>(p_kv, kv_ln_g, kv_ln_b);
    k_gemm128<<<dim3(8, 64), 256>>>(p_kv, attn_in_w + 512 * 512, attn_in_b + 512,
                                    p_KV, 8192, 1024, 512, 1024, 0, 1);
    cudaStreamWaitEvent(0, evP, 0);

    // ---- 25 iterations: main chain on default stream, out-branch on s2 ----
    for (int t = 0; t < NITER; t++) {
        int p = t & 1;
        k_phase1<<<256, 256>>>(idx_al, idx_ar, p);
        k_syngemm<<<dim3(32, SYN_KC), 256>>>(syn_w, p);
        k_phase3<<<32, 1024>>>(syn_ln_g, syn_ln_b, t);
        k_nlm<<<2048, 256>>>(tp1_b, tp2_b, t, p);
        cudaEventRecord(evI, 0);
        cudaStreamWaitEvent(s2, evI, 0);
        k_outgemm<<<dim3(4, 32), 256, 0, s2>>>(out_w, out_b, idx_ol, idx_or, dout, t);
        k_entropy<<<32, 256, 0, s2>>>(dout, t);
    }
    cudaEventRecord(evJ, s2);
    cudaStreamWaitEvent(0, evJ, 0);
}